// round 2
// baseline (speedup 1.0000x reference)
#include <cuda_runtime.h>
#include <cuda_bf16.h>
#include <math_constants.h>

#define B_MAX 4096
#define NF 50
#define E 128
#define A 64
#define M 8
#define FM (NF*M)   // 400

// Scratch (no cudaMalloc allowed)
__device__ float g_ak[B_MAX * FM];   // att_key [b][f][m]
__device__ float g_mx[FM];           // max over batch per (f,m)
__device__ float g_se[FM];           // sum exp over batch per (f,m)

// ---------------------------------------------------------------------------
// Kernel 1: stage friends in shared, fold uid_n into Key (kc[m][e]), then one
// thread per (f,m): register-resident 128-deep dot. No shuffle reductions in
// the hot loop; coalesced g_ak writes.
// ---------------------------------------------------------------------------
__global__ __launch_bounds__(256) void k_attkey(
    const int* __restrict__ iu, const int* __restrict__ iuf,
    const float* __restrict__ uidW, const float* __restrict__ Key,
    float* __restrict__ akout, int user_pad)
{
    int b = blockIdx.x;
    int tid = threadIdx.x, lane = tid & 31, warp = tid >> 5;

    __shared__ float sFe[NF][132];   // masked friend embeddings (padded rows)
    __shared__ float sKC[M][132];    // kc[m][e] = uid_n[e]*Key[e][m]
    __shared__ float sInv[NF + 2];   // 1/max(||fe||,eps)
    __shared__ float sred[8];

    // uid l2 norm
    float uv = 0.f;
    if (tid < E) uv = uidW[(size_t)iu[b] * E + tid];
    float p = uv * uv;
    #pragma unroll
    for (int o = 16; o; o >>= 1) p += __shfl_xor_sync(0xffffffffu, p, o);
    if (lane == 0) sred[warp] = p;
    __syncthreads();
    float n2 = 0.f;
    #pragma unroll
    for (int w = 0; w < 8; w++) n2 += sred[w];
    float inv = 1.f / fmaxf(sqrtf(n2), 1e-12f);

    if (tid < E) {
        float un = uv * inv;
        const float4* K4 = (const float4*)(Key + tid * M);
        float4 k0 = K4[0], k1 = K4[1];
        sKC[0][tid] = un * k0.x; sKC[1][tid] = un * k0.y;
        sKC[2][tid] = un * k0.z; sKC[3][tid] = un * k0.w;
        sKC[4][tid] = un * k1.x; sKC[5][tid] = un * k1.y;
        sKC[6][tid] = un * k1.z; sKC[7][tid] = un * k1.w;
    }

    // stage masked friends: warp per row
    const int* fids = iuf + b * NF;
    for (int f = warp; f < NF; f += 8) {
        int fid = fids[f];
        float fnm = (fid != user_pad) ? 1.f : 0.f;
        float4 v = *(const float4*)(uidW + (size_t)fid * E + lane * 4);
        v.x *= fnm; v.y *= fnm; v.z *= fnm; v.w *= fnm;
        *(float4*)&sFe[f][lane * 4] = v;
    }
    __syncthreads();

    // norms (one shuffle-tree per friend, 7 rounds total per warp)
    for (int f = warp; f < NF; f += 8) {
        float4 v = *(const float4*)&sFe[f][lane * 4];
        float s = v.x * v.x + v.y * v.y + v.z * v.z + v.w * v.w;
        #pragma unroll
        for (int o = 16; o; o >>= 1) s += __shfl_xor_sync(0xffffffffu, s, o);
        if (lane == 0) sInv[f] = 1.f / fmaxf(sqrtf(s), 1e-12f);
    }
    __syncthreads();

    // ak[f][m] = inv_f * sum_e sFe[f][e]*sKC[m][e]
    float* akb = akout + (size_t)b * FM;
    for (int idx = tid; idx < FM; idx += 256) {
        int f = idx >> 3, m = idx & 7;
        const float4* fe4 = (const float4*)sFe[f];
        const float4* kc4 = (const float4*)sKC[m];
        float a0 = 0.f, a1 = 0.f;
        #pragma unroll
        for (int e4 = 0; e4 < 32; e4 += 2) {
            float4 x = fe4[e4],     y = kc4[e4];
            a0 = fmaf(x.x, y.x, a0); a0 = fmaf(x.y, y.y, a0);
            a0 = fmaf(x.z, y.z, a0); a0 = fmaf(x.w, y.w, a0);
            float4 x1 = fe4[e4 + 1], y1 = kc4[e4 + 1];
            a1 = fmaf(x1.x, y1.x, a1); a1 = fmaf(x1.y, y1.y, a1);
            a1 = fmaf(x1.z, y1.z, a1); a1 = fmaf(x1.w, y1.w, a1);
        }
        akb[idx] = (a0 + a1) * sInv[f];
    }
}

// ---------------------------------------------------------------------------
// Kernel 2: batch-axis softmax stats. Block per friend f; float4 reads give
// 8 useful floats per 2 sectors. Two passes (max, then sumexp).
// ---------------------------------------------------------------------------
__global__ __launch_bounds__(256) void k_softstats(
    const float* __restrict__ ak, float* __restrict__ mx,
    float* __restrict__ se, int nb)
{
    int f = blockIdx.x;
    int tid = threadIdx.x, lane = tid & 31, warp = tid >> 5;
    __shared__ float sredm[8][8];
    __shared__ float sreds[8][8];

    float mv[8];
    #pragma unroll
    for (int m = 0; m < 8; m++) mv[m] = -CUDART_INF_F;
    for (int b = tid; b < nb; b += 256) {
        const float4* p = (const float4*)(ak + (size_t)b * FM + f * 8);
        float4 x0 = p[0], x1 = p[1];
        mv[0] = fmaxf(mv[0], x0.x); mv[1] = fmaxf(mv[1], x0.y);
        mv[2] = fmaxf(mv[2], x0.z); mv[3] = fmaxf(mv[3], x0.w);
        mv[4] = fmaxf(mv[4], x1.x); mv[5] = fmaxf(mv[5], x1.y);
        mv[6] = fmaxf(mv[6], x1.z); mv[7] = fmaxf(mv[7], x1.w);
    }
    #pragma unroll
    for (int m = 0; m < 8; m++) {
        #pragma unroll
        for (int o = 16; o; o >>= 1) mv[m] = fmaxf(mv[m], __shfl_xor_sync(0xffffffffu, mv[m], o));
    }
    if (lane == 0) {
        #pragma unroll
        for (int m = 0; m < 8; m++) sredm[warp][m] = mv[m];
    }
    __syncthreads();
    float mm[8];
    #pragma unroll
    for (int m = 0; m < 8; m++) {
        float v = sredm[0][m];
        #pragma unroll
        for (int w = 1; w < 8; w++) v = fmaxf(v, sredm[w][m]);
        mm[m] = v;
    }

    float sv[8] = {0,0,0,0,0,0,0,0};
    for (int b = tid; b < nb; b += 256) {
        const float4* p = (const float4*)(ak + (size_t)b * FM + f * 8);
        float4 x0 = p[0], x1 = p[1];
        sv[0] += __expf(x0.x - mm[0]); sv[1] += __expf(x0.y - mm[1]);
        sv[2] += __expf(x0.z - mm[2]); sv[3] += __expf(x0.w - mm[3]);
        sv[4] += __expf(x1.x - mm[4]); sv[5] += __expf(x1.y - mm[5]);
        sv[6] += __expf(x1.z - mm[6]); sv[7] += __expf(x1.w - mm[7]);
    }
    #pragma unroll
    for (int m = 0; m < 8; m++) {
        #pragma unroll
        for (int o = 16; o; o >>= 1) sv[m] += __shfl_xor_sync(0xffffffffu, sv[m], o);
    }
    if (lane == 0) {
        #pragma unroll
        for (int m = 0; m < 8; m++) sreds[warp][m] = sv[m];
    }
    __syncthreads();
    if (tid < 8) {
        float s = 0.f;
        #pragma unroll
        for (int w = 0; w < 8; w++) s += sreds[w][tid];
        mx[f * 8 + tid] = mm[tid];
        se[f * 8 + tid] = s;
    }
}

// ---------------------------------------------------------------------------
// Kernel 3: phase-tiled main pipeline. 256 threads, dynamic smem (~58KB).
// Phase A: all 50 f2 vectors -> shared. Phase B: [50x128]@[128x64] GEMM,
// WA column in 64 regs/thread, broadcast LDS of f2. Phase C: warp-per-f
// j reduction. Phase D: weighted sum + score.
// ---------------------------------------------------------------------------
__global__ __launch_bounds__(256) void k_main(
    const int* __restrict__ iu, const int* __restrict__ ii,
    const int* __restrict__ iuf, const float* __restrict__ uidW,
    const float* __restrict__ iidW, const float* __restrict__ ibias,
    const float* __restrict__ Memw, const float* __restrict__ WA,
    const float* __restrict__ BA, const float* __restrict__ Uo,
    const float* __restrict__ ak, const float* __restrict__ mx,
    const float* __restrict__ se, float* __restrict__ out, int user_pad)
{
    int b = blockIdx.x, tid = threadIdx.x, lane = tid & 31, warp = tid >> 5;
    int a = tid & 63, half = (tid >> 6) & 1, g = tid >> 7;
    int e = tid & 127;

    extern __shared__ float sm[];
    float* sF2  = sm;                 // [50][128]
    float* sHP  = sm + NF * E;        // [50][128]
    float* sMem = sHP + NF * E;       // [8][128]
    float* sAm  = sMem + M * E;       // [400]
    float* sJ   = sAm + FM;           // [50] (+pad)
    float* sBA  = sJ + 56;            // [64]
    float* sUo  = sBA + A;            // [64]
    float* sred = sUo + A;            // [8]

    for (int i = tid; i < M * E; i += 256) sMem[i] = Memw[i];
    if (tid < A) { sBA[tid] = BA[tid]; sUo[tid] = Uo[tid]; }

    const int* fids = iuf + b * NF;
    const float* akb = ak + (size_t)b * FM;
    for (int i = tid; i < FM; i += 256) {
        int f = i >> 3;
        float fnm = (fids[f] != user_pad) ? 1.f : 0.f;
        sAm[i] = fnm * __expf(akb[i] - mx[i]) / se[i];
    }

    // WA column (a) for this thread's e-half -> 64 registers
    float wreg[64];
    #pragma unroll
    for (int e0 = 0; e0 < 64; e0++) wreg[e0] = WA[(half * 64 + e0) * A + a];
    __syncthreads();

    // Phase A: f2 for all friends (group g owns f = g mod 2)
    for (int f = g; f < NF; f += 2) {
        int fid = fids[f];
        float fnm = (fid != user_pad) ? 1.f : 0.f;
        float fe = uidW[(size_t)fid * E + e] * fnm;
        float f1 = 0.f;
        #pragma unroll
        for (int m = 0; m < M; m++) f1 = fmaf(sAm[f * 8 + m], sMem[m * E + e], f1);
        sF2[f * E + e] = f1 * fe;
    }
    __syncthreads();

    // Phase B: hp(f, a, half) = sum_{e in half} f2[e]*WA[e][a]
    for (int f = g; f < NF; f += 2) {
        const float4* F4 = (const float4*)&sF2[f * E + half * 64];
        float acc0 = 0.f, acc1 = 0.f;
        #pragma unroll
        for (int e4 = 0; e4 < 16; e4 += 2) {
            float4 q = F4[e4];
            acc0 = fmaf(q.x, wreg[e4 * 4 + 0], acc0);
            acc0 = fmaf(q.y, wreg[e4 * 4 + 1], acc0);
            acc0 = fmaf(q.z, wreg[e4 * 4 + 2], acc0);
            acc0 = fmaf(q.w, wreg[e4 * 4 + 3], acc0);
            float4 q2 = F4[e4 + 1];
            acc1 = fmaf(q2.x, wreg[e4 * 4 + 4], acc1);
            acc1 = fmaf(q2.y, wreg[e4 * 4 + 5], acc1);
            acc1 = fmaf(q2.z, wreg[e4 * 4 + 6], acc1);
            acc1 = fmaf(q2.w, wreg[e4 * 4 + 7], acc1);
        }
        sHP[f * E + half * 64 + a] = acc0 + acc1;
    }
    __syncthreads();

    // Phase C: j[f] (warp per friend, strided)
    for (int f = warp; f < NF; f += 8) {
        float h0 = sHP[f * E + lane]      + sHP[f * E + 64 + lane] + sBA[lane];
        float h1 = sHP[f * E + 32 + lane] + sHP[f * E + 96 + lane] + sBA[32 + lane];
        h0 = fmaxf(h0, 0.f); h1 = fmaxf(h1, 0.f);
        float jp = h0 * sUo[lane] + h1 * sUo[32 + lane];
        #pragma unroll
        for (int o = 16; o; o >>= 1) jp += __shfl_xor_sync(0xffffffffu, jp, o);
        if (lane == 0) {
            float fnm = (fids[f] != user_pad) ? 1.f : 0.f;
            sJ[f] = fnm * __expf(jp);
        }
    }
    __syncthreads();

    // Phase D: weighted friend sum + score
    if (tid < 128) {
        float jsum = 0.f;
        #pragma unroll 10
        for (int f = 0; f < NF; f++) jsum += sJ[f];
        float facc = 0.f;
        #pragma unroll 10
        for (int f = 0; f < NF; f++) facc = fmaf(sJ[f], sF2[f * E + e], facc);
        float user = uidW[(size_t)iu[b] * E + e] + facc / (jsum + 1e-8f);
        int it = ii[b];
        float pp = user * iidW[(size_t)it * E + e];
        #pragma unroll
        for (int o = 16; o; o >>= 1) pp += __shfl_xor_sync(0xffffffffu, pp, o);
        if (lane == 0) sred[warp] = pp;
    }
    __syncthreads();
    if (tid == 0) out[b] = sred[0] + sred[1] + sred[2] + sred[3] + ibias[ii[b]];
}

// ---------------------------------------------------------------------------
extern "C" void kernel_launch(void* const* d_in, const int* in_sizes, int n_in,
                              void* d_out, int out_size)
{
    const int*   input_u  = (const int*)d_in[0];
    const int*   input_i  = (const int*)d_in[1];
    const int*   input_uf = (const int*)d_in[2];
    const float* uidW     = (const float*)d_in[3];
    const float* iidW     = (const float*)d_in[4];
    const float* i_bias   = (const float*)d_in[5];
    const float* Key      = (const float*)d_in[6];
    const float* Memw     = (const float*)d_in[7];
    const float* WA       = (const float*)d_in[8];
    const float* BA       = (const float*)d_in[9];
    const float* Uo       = (const float*)d_in[10];
    float* out = (float*)d_out;

    int nb = in_sizes[0];
    int user_pad = in_sizes[3] / E - 1;

    float *g_ak_p, *g_mx_p, *g_se_p;
    cudaGetSymbolAddress((void**)&g_ak_p, g_ak);
    cudaGetSymbolAddress((void**)&g_mx_p, g_mx);
    cudaGetSymbolAddress((void**)&g_se_p, g_se);

    const int kmain_smem = (NF*E + NF*E + M*E + FM + 56 + A + A + 8) * 4;
    static int attr_set = 0;
    if (!attr_set) {
        cudaFuncSetAttribute(k_main, cudaFuncAttributeMaxDynamicSharedMemorySize, kmain_smem);
        attr_set = 1;
    }

    k_attkey<<<nb, 256>>>(input_u, input_uf, uidW, Key, g_ak_p, user_pad);
    k_softstats<<<NF, 256>>>(g_ak_p, g_mx_p, g_se_p, nb);
    k_main<<<nb, 256, kmain_smem>>>(input_u, input_i, input_uf, uidW, iidW, i_bias,
                                    Memw, WA, BA, Uo, g_ak_p, g_mx_p, g_se_p, out, user_pad);
}

// round 3
// speedup vs baseline: 1.2840x; 1.2840x over previous
#include <cuda_runtime.h>
#include <cuda_bf16.h>
#include <math_constants.h>

#define B_MAX 4096
#define NF 50
#define E 128
#define A 64
#define M 8
#define FM (NF*M)   // 400

// Scratch (no cudaMalloc allowed)
__device__ float g_ak[B_MAX * FM];   // att_key [b][f][m]
__device__ float g_mx[FM];           // max over batch per (f,m)
__device__ float g_se[FM];           // sum exp over batch per (f,m)

// ---------------------------------------------------------------------------
// Kernel 1: stage friends in shared, fold uid_n into Key (kc[m][e]), then one
// thread per (f,m): 128-deep dot from shared. Register-capped for occupancy.
// ---------------------------------------------------------------------------
__global__ __launch_bounds__(256, 4) void k_attkey(
    const int* __restrict__ iu, const int* __restrict__ iuf,
    const float* __restrict__ uidW, const float* __restrict__ Key,
    float* __restrict__ akout, int user_pad)
{
    int b = blockIdx.x;
    int tid = threadIdx.x, lane = tid & 31, warp = tid >> 5;

    __shared__ float sFe[NF][132];   // masked friend embeddings (padded rows)
    __shared__ float sKC[M][132];    // kc[m][e] = uid_n[e]*Key[e][m]
    __shared__ float sInv[NF + 2];   // 1/max(||fe||,eps)
    __shared__ float sred[8];

    // uid l2 norm
    float uv = 0.f;
    if (tid < E) uv = uidW[(size_t)iu[b] * E + tid];
    float p = uv * uv;
    #pragma unroll
    for (int o = 16; o; o >>= 1) p += __shfl_xor_sync(0xffffffffu, p, o);
    if (lane == 0) sred[warp] = p;
    __syncthreads();
    float n2 = 0.f;
    #pragma unroll
    for (int w = 0; w < 8; w++) n2 += sred[w];
    float inv = 1.f / fmaxf(sqrtf(n2), 1e-12f);

    if (tid < E) {
        float un = uv * inv;
        const float4* K4 = (const float4*)(Key + tid * M);
        float4 k0 = K4[0], k1 = K4[1];
        sKC[0][tid] = un * k0.x; sKC[1][tid] = un * k0.y;
        sKC[2][tid] = un * k0.z; sKC[3][tid] = un * k0.w;
        sKC[4][tid] = un * k1.x; sKC[5][tid] = un * k1.y;
        sKC[6][tid] = un * k1.z; sKC[7][tid] = un * k1.w;
    }

    // stage masked friends: warp per row
    const int* fids = iuf + b * NF;
    for (int f = warp; f < NF; f += 8) {
        int fid = fids[f];
        float fnm = (fid != user_pad) ? 1.f : 0.f;
        float4 v = *(const float4*)(uidW + (size_t)fid * E + lane * 4);
        v.x *= fnm; v.y *= fnm; v.z *= fnm; v.w *= fnm;
        *(float4*)&sFe[f][lane * 4] = v;
    }
    __syncthreads();

    // norms (one shuffle-tree per friend per owning warp)
    for (int f = warp; f < NF; f += 8) {
        float4 v = *(const float4*)&sFe[f][lane * 4];
        float s = v.x * v.x + v.y * v.y + v.z * v.z + v.w * v.w;
        #pragma unroll
        for (int o = 16; o; o >>= 1) s += __shfl_xor_sync(0xffffffffu, s, o);
        if (lane == 0) sInv[f] = 1.f / fmaxf(sqrtf(s), 1e-12f);
    }
    __syncthreads();

    // ak[f][m] = inv_f * sum_e sFe[f][e]*sKC[m][e]  (bounded unroll -> low regs)
    float* akb = akout + (size_t)b * FM;
    for (int idx = tid; idx < FM; idx += 256) {
        int f = idx >> 3, m = idx & 7;
        const float4* fe4 = (const float4*)sFe[f];
        const float4* kc4 = (const float4*)sKC[m];
        float a0 = 0.f, a1 = 0.f;
        #pragma unroll 4
        for (int e4 = 0; e4 < 32; e4 += 2) {
            float4 x = fe4[e4],     y = kc4[e4];
            a0 = fmaf(x.x, y.x, a0); a0 = fmaf(x.y, y.y, a0);
            a0 = fmaf(x.z, y.z, a0); a0 = fmaf(x.w, y.w, a0);
            float4 x1 = fe4[e4 + 1], y1 = kc4[e4 + 1];
            a1 = fmaf(x1.x, y1.x, a1); a1 = fmaf(x1.y, y1.y, a1);
            a1 = fmaf(x1.z, y1.z, a1); a1 = fmaf(x1.w, y1.w, a1);
        }
        akb[idx] = (a0 + a1) * sInv[f];
    }
}

// ---------------------------------------------------------------------------
// Kernel 2: batch-axis softmax stats. Block per friend f; float4 reads.
// ---------------------------------------------------------------------------
__global__ __launch_bounds__(256) void k_softstats(
    const float* __restrict__ ak, float* __restrict__ mx,
    float* __restrict__ se, int nb)
{
    int f = blockIdx.x;
    int tid = threadIdx.x, lane = tid & 31, warp = tid >> 5;
    __shared__ float sredm[8][8];
    __shared__ float sreds[8][8];

    float mv[8];
    #pragma unroll
    for (int m = 0; m < 8; m++) mv[m] = -CUDART_INF_F;
    for (int b = tid; b < nb; b += 256) {
        const float4* p = (const float4*)(ak + (size_t)b * FM + f * 8);
        float4 x0 = p[0], x1 = p[1];
        mv[0] = fmaxf(mv[0], x0.x); mv[1] = fmaxf(mv[1], x0.y);
        mv[2] = fmaxf(mv[2], x0.z); mv[3] = fmaxf(mv[3], x0.w);
        mv[4] = fmaxf(mv[4], x1.x); mv[5] = fmaxf(mv[5], x1.y);
        mv[6] = fmaxf(mv[6], x1.z); mv[7] = fmaxf(mv[7], x1.w);
    }
    #pragma unroll
    for (int m = 0; m < 8; m++) {
        #pragma unroll
        for (int o = 16; o; o >>= 1) mv[m] = fmaxf(mv[m], __shfl_xor_sync(0xffffffffu, mv[m], o));
    }
    if (lane == 0) {
        #pragma unroll
        for (int m = 0; m < 8; m++) sredm[warp][m] = mv[m];
    }
    __syncthreads();
    float mm[8];
    #pragma unroll
    for (int m = 0; m < 8; m++) {
        float v = sredm[0][m];
        #pragma unroll
        for (int w = 1; w < 8; w++) v = fmaxf(v, sredm[w][m]);
        mm[m] = v;
    }

    float sv[8] = {0,0,0,0,0,0,0,0};
    for (int b = tid; b < nb; b += 256) {
        const float4* p = (const float4*)(ak + (size_t)b * FM + f * 8);
        float4 x0 = p[0], x1 = p[1];
        sv[0] += __expf(x0.x - mm[0]); sv[1] += __expf(x0.y - mm[1]);
        sv[2] += __expf(x0.z - mm[2]); sv[3] += __expf(x0.w - mm[3]);
        sv[4] += __expf(x1.x - mm[4]); sv[5] += __expf(x1.y - mm[5]);
        sv[6] += __expf(x1.z - mm[6]); sv[7] += __expf(x1.w - mm[7]);
    }
    #pragma unroll
    for (int m = 0; m < 8; m++) {
        #pragma unroll
        for (int o = 16; o; o >>= 1) sv[m] += __shfl_xor_sync(0xffffffffu, sv[m], o);
    }
    if (lane == 0) {
        #pragma unroll
        for (int m = 0; m < 8; m++) sreds[warp][m] = sv[m];
    }
    __syncthreads();
    if (tid < 8) {
        float s = 0.f;
        #pragma unroll
        for (int w = 0; w < 8; w++) s += sreds[w][tid];
        mx[f * 8 + tid] = mm[tid];
        se[f * 8 + tid] = s;
    }
}

// ---------------------------------------------------------------------------
// Kernel 3: phase-tiled main pipeline (unchanged from R2 — it improved).
// ---------------------------------------------------------------------------
__global__ __launch_bounds__(256) void k_main(
    const int* __restrict__ iu, const int* __restrict__ ii,
    const int* __restrict__ iuf, const float* __restrict__ uidW,
    const float* __restrict__ iidW, const float* __restrict__ ibias,
    const float* __restrict__ Memw, const float* __restrict__ WA,
    const float* __restrict__ BA, const float* __restrict__ Uo,
    const float* __restrict__ ak, const float* __restrict__ mx,
    const float* __restrict__ se, float* __restrict__ out, int user_pad)
{
    int b = blockIdx.x, tid = threadIdx.x, lane = tid & 31, warp = tid >> 5;
    int a = tid & 63, half = (tid >> 6) & 1, g = tid >> 7;
    int e = tid & 127;

    extern __shared__ float sm[];
    float* sF2  = sm;                 // [50][128]
    float* sHP  = sm + NF * E;        // [50][128]
    float* sMem = sHP + NF * E;       // [8][128]
    float* sAm  = sMem + M * E;       // [400]
    float* sJ   = sAm + FM;           // [50] (+pad)
    float* sBA  = sJ + 56;            // [64]
    float* sUo  = sBA + A;            // [64]
    float* sred = sUo + A;            // [8]

    for (int i = tid; i < M * E; i += 256) sMem[i] = Memw[i];
    if (tid < A) { sBA[tid] = BA[tid]; sUo[tid] = Uo[tid]; }

    const int* fids = iuf + b * NF;
    const float* akb = ak + (size_t)b * FM;
    for (int i = tid; i < FM; i += 256) {
        int f = i >> 3;
        float fnm = (fids[f] != user_pad) ? 1.f : 0.f;
        sAm[i] = fnm * __expf(akb[i] - mx[i]) / se[i];
    }

    // WA column (a) for this thread's e-half -> 64 registers
    float wreg[64];
    #pragma unroll
    for (int e0 = 0; e0 < 64; e0++) wreg[e0] = WA[(half * 64 + e0) * A + a];
    __syncthreads();

    // Phase A: f2 for all friends (group g owns f = g mod 2)
    for (int f = g; f < NF; f += 2) {
        int fid = fids[f];
        float fnm = (fid != user_pad) ? 1.f : 0.f;
        float fe = uidW[(size_t)fid * E + e] * fnm;
        float f1 = 0.f;
        #pragma unroll
        for (int m = 0; m < M; m++) f1 = fmaf(sAm[f * 8 + m], sMem[m * E + e], f1);
        sF2[f * E + e] = f1 * fe;
    }
    __syncthreads();

    // Phase B: hp(f, a, half) = sum_{e in half} f2[e]*WA[e][a]
    for (int f = g; f < NF; f += 2) {
        const float4* F4 = (const float4*)&sF2[f * E + half * 64];
        float acc0 = 0.f, acc1 = 0.f;
        #pragma unroll
        for (int e4 = 0; e4 < 16; e4 += 2) {
            float4 q = F4[e4];
            acc0 = fmaf(q.x, wreg[e4 * 4 + 0], acc0);
            acc0 = fmaf(q.y, wreg[e4 * 4 + 1], acc0);
            acc0 = fmaf(q.z, wreg[e4 * 4 + 2], acc0);
            acc0 = fmaf(q.w, wreg[e4 * 4 + 3], acc0);
            float4 q2 = F4[e4 + 1];
            acc1 = fmaf(q2.x, wreg[e4 * 4 + 4], acc1);
            acc1 = fmaf(q2.y, wreg[e4 * 4 + 5], acc1);
            acc1 = fmaf(q2.z, wreg[e4 * 4 + 6], acc1);
            acc1 = fmaf(q2.w, wreg[e4 * 4 + 7], acc1);
        }
        sHP[f * E + half * 64 + a] = acc0 + acc1;
    }
    __syncthreads();

    // Phase C: j[f] (warp per friend, strided)
    for (int f = warp; f < NF; f += 8) {
        float h0 = sHP[f * E + lane]      + sHP[f * E + 64 + lane] + sBA[lane];
        float h1 = sHP[f * E + 32 + lane] + sHP[f * E + 96 + lane] + sBA[32 + lane];
        h0 = fmaxf(h0, 0.f); h1 = fmaxf(h1, 0.f);
        float jp = h0 * sUo[lane] + h1 * sUo[32 + lane];
        #pragma unroll
        for (int o = 16; o; o >>= 1) jp += __shfl_xor_sync(0xffffffffu, jp, o);
        if (lane == 0) {
            float fnm = (fids[f] != user_pad) ? 1.f : 0.f;
            sJ[f] = fnm * __expf(jp);
        }
    }
    __syncthreads();

    // Phase D: weighted friend sum + score
    if (tid < 128) {
        float jsum = 0.f;
        #pragma unroll 10
        for (int f = 0; f < NF; f++) jsum += sJ[f];
        float facc = 0.f;
        #pragma unroll 10
        for (int f = 0; f < NF; f++) facc = fmaf(sJ[f], sF2[f * E + e], facc);
        float user = uidW[(size_t)iu[b] * E + e] + facc / (jsum + 1e-8f);
        int it = ii[b];
        float pp = user * iidW[(size_t)it * E + e];
        #pragma unroll
        for (int o = 16; o; o >>= 1) pp += __shfl_xor_sync(0xffffffffu, pp, o);
        if (lane == 0) sred[warp] = pp;
    }
    __syncthreads();
    if (tid == 0) out[b] = sred[0] + sred[1] + sred[2] + sred[3] + ibias[ii[b]];
}

// ---------------------------------------------------------------------------
extern "C" void kernel_launch(void* const* d_in, const int* in_sizes, int n_in,
                              void* d_out, int out_size)
{
    const int*   input_u  = (const int*)d_in[0];
    const int*   input_i  = (const int*)d_in[1];
    const int*   input_uf = (const int*)d_in[2];
    const float* uidW     = (const float*)d_in[3];
    const float* iidW     = (const float*)d_in[4];
    const float* i_bias   = (const float*)d_in[5];
    const float* Key      = (const float*)d_in[6];
    const float* Memw     = (const float*)d_in[7];
    const float* WA       = (const float*)d_in[8];
    const float* BA       = (const float*)d_in[9];
    const float* Uo       = (const float*)d_in[10];
    float* out = (float*)d_out;

    int nb = in_sizes[0];
    int user_pad = in_sizes[3] / E - 1;

    float *g_ak_p, *g_mx_p, *g_se_p;
    cudaGetSymbolAddress((void**)&g_ak_p, g_ak);
    cudaGetSymbolAddress((void**)&g_mx_p, g_mx);
    cudaGetSymbolAddress((void**)&g_se_p, g_se);

    const int kmain_smem = (NF*E + NF*E + M*E + FM + 56 + A + A + 8) * 4;
    static int attr_set = 0;
    if (!attr_set) {
        cudaFuncSetAttribute(k_main, cudaFuncAttributeMaxDynamicSharedMemorySize, kmain_smem);
        attr_set = 1;
    }

    k_attkey<<<nb, 256>>>(input_u, input_uf, uidW, Key, g_ak_p, user_pad);
    k_softstats<<<NF, 256>>>(g_ak_p, g_mx_p, g_se_p, nb);
    k_main<<<nb, 256, kmain_smem>>>(input_u, input_i, input_uf, uidW, iidW, i_bias,
                                    Memw, WA, BA, Uo, g_ak_p, g_mx_p, g_se_p, out, user_pad);
}

// round 4
// speedup vs baseline: 1.3220x; 1.0296x over previous
#include <cuda_runtime.h>
#include <cuda_bf16.h>
#include <math_constants.h>

#define B_MAX 4096
#define NF 50
#define E 128
#define A 64
#define M 8
#define FM (NF*M)   // 400

// Scratch (no cudaMalloc allowed)
__device__ float g_ak[B_MAX * FM];   // att_key [b][f][m]
__device__ float g_mx[FM];           // max over batch per (f,m)
__device__ float g_se[FM];           // sum exp over batch per (f,m)
__device__ float g_mxq[4 * FM];      // per-quarter partial max
__device__ float g_seq[4 * FM];      // per-quarter partial sumexp

#define FFMA2(d, a, b, c) \
    asm("fma.rn.f32x2 %0, %1, %2, %3;" : "=l"(d) : "l"(a), "l"(b), "l"(c))

__device__ __forceinline__ unsigned long long pack2(float lo, float hi) {
    unsigned long long r;
    asm("mov.b64 %0, {%1, %2};" : "=l"(r) : "f"(lo), "f"(hi));
    return r;
}
__device__ __forceinline__ float unpack_sum(unsigned long long v) {
    float lo, hi;
    asm("mov.b64 {%0, %1}, %2;" : "=f"(lo), "=f"(hi) : "l"(v));
    return lo + hi;
}

// ---------------------------------------------------------------------------
// Kernel 1: stage friends in shared, fold uid_n into Key (kc[m][e]), then one
// thread per (f,m): 128-deep dot from shared. Register-capped for occupancy.
// ---------------------------------------------------------------------------
__global__ __launch_bounds__(256, 4) void k_attkey(
    const int* __restrict__ iu, const int* __restrict__ iuf,
    const float* __restrict__ uidW, const float* __restrict__ Key,
    float* __restrict__ akout, int user_pad)
{
    int b = blockIdx.x;
    int tid = threadIdx.x, lane = tid & 31, warp = tid >> 5;

    __shared__ float sFe[NF][132];
    __shared__ float sKC[M][132];
    __shared__ float sInv[NF + 2];
    __shared__ float sred[8];

    float uv = 0.f;
    if (tid < E) uv = uidW[(size_t)iu[b] * E + tid];
    float p = uv * uv;
    #pragma unroll
    for (int o = 16; o; o >>= 1) p += __shfl_xor_sync(0xffffffffu, p, o);
    if (lane == 0) sred[warp] = p;
    __syncthreads();
    float n2 = 0.f;
    #pragma unroll
    for (int w = 0; w < 8; w++) n2 += sred[w];
    float inv = 1.f / fmaxf(sqrtf(n2), 1e-12f);

    if (tid < E) {
        float un = uv * inv;
        const float4* K4 = (const float4*)(Key + tid * M);
        float4 k0 = K4[0], k1 = K4[1];
        sKC[0][tid] = un * k0.x; sKC[1][tid] = un * k0.y;
        sKC[2][tid] = un * k0.z; sKC[3][tid] = un * k0.w;
        sKC[4][tid] = un * k1.x; sKC[5][tid] = un * k1.y;
        sKC[6][tid] = un * k1.z; sKC[7][tid] = un * k1.w;
    }

    const int* fids = iuf + b * NF;
    for (int f = warp; f < NF; f += 8) {
        int fid = fids[f];
        float fnm = (fid != user_pad) ? 1.f : 0.f;
        float4 v = *(const float4*)(uidW + (size_t)fid * E + lane * 4);
        v.x *= fnm; v.y *= fnm; v.z *= fnm; v.w *= fnm;
        *(float4*)&sFe[f][lane * 4] = v;
    }
    __syncthreads();

    for (int f = warp; f < NF; f += 8) {
        float4 v = *(const float4*)&sFe[f][lane * 4];
        float s = v.x * v.x + v.y * v.y + v.z * v.z + v.w * v.w;
        #pragma unroll
        for (int o = 16; o; o >>= 1) s += __shfl_xor_sync(0xffffffffu, s, o);
        if (lane == 0) sInv[f] = 1.f / fmaxf(sqrtf(s), 1e-12f);
    }
    __syncthreads();

    float* akb = akout + (size_t)b * FM;
    for (int idx = tid; idx < FM; idx += 256) {
        int f = idx >> 3, m = idx & 7;
        const float4* fe4 = (const float4*)sFe[f];
        const float4* kc4 = (const float4*)sKC[m];
        float a0 = 0.f, a1 = 0.f;
        #pragma unroll 4
        for (int e4 = 0; e4 < 32; e4 += 2) {
            float4 x = fe4[e4],     y = kc4[e4];
            a0 = fmaf(x.x, y.x, a0); a0 = fmaf(x.y, y.y, a0);
            a0 = fmaf(x.z, y.z, a0); a0 = fmaf(x.w, y.w, a0);
            float4 x1 = fe4[e4 + 1], y1 = kc4[e4 + 1];
            a1 = fmaf(x1.x, y1.x, a1); a1 = fmaf(x1.y, y1.y, a1);
            a1 = fmaf(x1.z, y1.z, a1); a1 = fmaf(x1.w, y1.w, a1);
        }
        akb[idx] = (a0 + a1) * sInv[f];
    }
}

// ---------------------------------------------------------------------------
// Kernel 2a: partial softmax stats per (friend, batch-quarter). 200 blocks.
// ---------------------------------------------------------------------------
__global__ __launch_bounds__(256) void k_softstats_part(
    const float* __restrict__ ak, float* __restrict__ mxq,
    float* __restrict__ seq, int nb)
{
    int f = blockIdx.x, q = blockIdx.y;
    int b0 = (nb * q) >> 2, b1 = (nb * (q + 1)) >> 2;
    int tid = threadIdx.x, lane = tid & 31, warp = tid >> 5;
    __shared__ float sredm[8][8];
    __shared__ float sreds[8][8];

    float mv[8];
    #pragma unroll
    for (int m = 0; m < 8; m++) mv[m] = -CUDART_INF_F;
    for (int b = b0 + tid; b < b1; b += 256) {
        const float4* p = (const float4*)(ak + (size_t)b * FM + f * 8);
        float4 x0 = p[0], x1 = p[1];
        mv[0] = fmaxf(mv[0], x0.x); mv[1] = fmaxf(mv[1], x0.y);
        mv[2] = fmaxf(mv[2], x0.z); mv[3] = fmaxf(mv[3], x0.w);
        mv[4] = fmaxf(mv[4], x1.x); mv[5] = fmaxf(mv[5], x1.y);
        mv[6] = fmaxf(mv[6], x1.z); mv[7] = fmaxf(mv[7], x1.w);
    }
    #pragma unroll
    for (int m = 0; m < 8; m++) {
        #pragma unroll
        for (int o = 16; o; o >>= 1) mv[m] = fmaxf(mv[m], __shfl_xor_sync(0xffffffffu, mv[m], o));
    }
    if (lane == 0) {
        #pragma unroll
        for (int m = 0; m < 8; m++) sredm[warp][m] = mv[m];
    }
    __syncthreads();
    float mm[8];
    #pragma unroll
    for (int m = 0; m < 8; m++) {
        float v = sredm[0][m];
        #pragma unroll
        for (int w = 1; w < 8; w++) v = fmaxf(v, sredm[w][m]);
        mm[m] = v;
    }

    float sv[8] = {0,0,0,0,0,0,0,0};
    for (int b = b0 + tid; b < b1; b += 256) {
        const float4* p = (const float4*)(ak + (size_t)b * FM + f * 8);
        float4 x0 = p[0], x1 = p[1];
        sv[0] += __expf(x0.x - mm[0]); sv[1] += __expf(x0.y - mm[1]);
        sv[2] += __expf(x0.z - mm[2]); sv[3] += __expf(x0.w - mm[3]);
        sv[4] += __expf(x1.x - mm[4]); sv[5] += __expf(x1.y - mm[5]);
        sv[6] += __expf(x1.z - mm[6]); sv[7] += __expf(x1.w - mm[7]);
    }
    #pragma unroll
    for (int m = 0; m < 8; m++) {
        #pragma unroll
        for (int o = 16; o; o >>= 1) sv[m] += __shfl_xor_sync(0xffffffffu, sv[m], o);
    }
    if (lane == 0) {
        #pragma unroll
        for (int m = 0; m < 8; m++) sreds[warp][m] = sv[m];
    }
    __syncthreads();
    if (tid < 8) {
        float s = 0.f;
        #pragma unroll
        for (int w = 0; w < 8; w++) s += sreds[w][tid];
        mxq[q * FM + f * 8 + tid] = mm[tid];
        seq[q * FM + f * 8 + tid] = s;
    }
}

// Kernel 2b: combine 4 quarter-partials (rescaled by exp(mq - m_global)).
__global__ __launch_bounds__(512) void k_softstats_comb(
    const float* __restrict__ mxq, const float* __restrict__ seq,
    float* __restrict__ mx, float* __restrict__ se)
{
    int i = threadIdx.x;
    if (i >= FM) return;
    float m0 = mxq[i], m1 = mxq[FM + i], m2 = mxq[2 * FM + i], m3 = mxq[3 * FM + i];
    float mg = fmaxf(fmaxf(m0, m1), fmaxf(m2, m3));
    float s = seq[i] * __expf(m0 - mg) + seq[FM + i] * __expf(m1 - mg)
            + seq[2 * FM + i] * __expf(m2 - mg) + seq[3 * FM + i] * __expf(m3 - mg);
    mx[i] = mg;
    se[i] = s;
}

// ---------------------------------------------------------------------------
// Kernel 3: phase-tiled main pipeline; Phase B uses packed fma.rn.f32x2.
// ---------------------------------------------------------------------------
__global__ __launch_bounds__(256) void k_main(
    const int* __restrict__ iu, const int* __restrict__ ii,
    const int* __restrict__ iuf, const float* __restrict__ uidW,
    const float* __restrict__ iidW, const float* __restrict__ ibias,
    const float* __restrict__ Memw, const float* __restrict__ WA,
    const float* __restrict__ BA, const float* __restrict__ Uo,
    const float* __restrict__ ak, const float* __restrict__ mx,
    const float* __restrict__ se, float* __restrict__ out, int user_pad)
{
    int b = blockIdx.x, tid = threadIdx.x, lane = tid & 31, warp = tid >> 5;
    int a = tid & 63, half = (tid >> 6) & 1, g = tid >> 7;
    int e = tid & 127;

    extern __shared__ float sm[];
    float* sF2  = sm;                 // [50][128]
    float* sHP  = sm + NF * E;        // [50][128]
    float* sMem = sHP + NF * E;       // [8][128]
    float* sAm  = sMem + M * E;       // [400]
    float* sJ   = sAm + FM;           // [50] (+pad)
    float* sBA  = sJ + 56;            // [64]
    float* sUo  = sBA + A;            // [64]
    float* sred = sUo + A;            // [8]

    for (int i = tid; i < M * E; i += 256) sMem[i] = Memw[i];
    if (tid < A) { sBA[tid] = BA[tid]; sUo[tid] = Uo[tid]; }

    const int* fids = iuf + b * NF;
    const float* akb = ak + (size_t)b * FM;
    for (int i = tid; i < FM; i += 256) {
        int f = i >> 3;
        float fnm = (fids[f] != user_pad) ? 1.f : 0.f;
        sAm[i] = fnm * __expf(akb[i] - mx[i]) / se[i];
    }

    // Packed WA column pairs: wp[k] = (WA[2k][a], WA[2k+1][a]) for this e-half
    unsigned long long wp[32];
    #pragma unroll
    for (int k = 0; k < 32; k++) {
        int e0 = half * 64 + 2 * k;
        wp[k] = pack2(WA[e0 * A + a], WA[(e0 + 1) * A + a]);
    }
    __syncthreads();

    // Phase A: f2 for all friends
    for (int f = g; f < NF; f += 2) {
        int fid = fids[f];
        float fnm = (fid != user_pad) ? 1.f : 0.f;
        float fe = uidW[(size_t)fid * E + e] * fnm;
        float f1 = 0.f;
        #pragma unroll
        for (int m = 0; m < M; m++) f1 = fmaf(sAm[f * 8 + m], sMem[m * E + e], f1);
        sF2[f * E + e] = f1 * fe;
    }
    __syncthreads();

    // Phase B: hp(f, a, half) via packed f32x2 FMA
    for (int f = g; f < NF; f += 2) {
        const ulonglong2* F2 = (const ulonglong2*)&sF2[f * E + half * 64];
        unsigned long long acc0 = 0ull, acc1 = 0ull;  // (0.f,0.f) bit pattern
        #pragma unroll
        for (int k = 0; k < 8; k++) {
            ulonglong2 v = F2[k];
            FFMA2(acc0, v.x, wp[2 * k], acc0);
            FFMA2(acc1, v.y, wp[2 * k + 1], acc1);
        }
        #pragma unroll
        for (int k = 8; k < 16; k++) {
            ulonglong2 v = F2[k];
            FFMA2(acc0, v.x, wp[2 * k], acc0);
            FFMA2(acc1, v.y, wp[2 * k + 1], acc1);
        }
        sHP[f * E + half * 64 + a] = unpack_sum(acc0) + unpack_sum(acc1);
    }
    __syncthreads();

    // Phase C: j[f] (warp per friend)
    for (int f = warp; f < NF; f += 8) {
        float h0 = sHP[f * E + lane]      + sHP[f * E + 64 + lane] + sBA[lane];
        float h1 = sHP[f * E + 32 + lane] + sHP[f * E + 96 + lane] + sBA[32 + lane];
        h0 = fmaxf(h0, 0.f); h1 = fmaxf(h1, 0.f);
        float jp = h0 * sUo[lane] + h1 * sUo[32 + lane];
        #pragma unroll
        for (int o = 16; o; o >>= 1) jp += __shfl_xor_sync(0xffffffffu, jp, o);
        if (lane == 0) {
            float fnm = (fids[f] != user_pad) ? 1.f : 0.f;
            sJ[f] = fnm * __expf(jp);
        }
    }
    __syncthreads();

    // Phase D: weighted friend sum + score
    if (tid < 128) {
        float jsum = 0.f;
        #pragma unroll 10
        for (int f = 0; f < NF; f++) jsum += sJ[f];
        float facc = 0.f;
        #pragma unroll 10
        for (int f = 0; f < NF; f++) facc = fmaf(sJ[f], sF2[f * E + e], facc);
        float user = uidW[(size_t)iu[b] * E + e] + facc / (jsum + 1e-8f);
        int it = ii[b];
        float pp = user * iidW[(size_t)it * E + e];
        #pragma unroll
        for (int o = 16; o; o >>= 1) pp += __shfl_xor_sync(0xffffffffu, pp, o);
        if (lane == 0) sred[warp] = pp;
    }
    __syncthreads();
    if (tid == 0) out[b] = sred[0] + sred[1] + sred[2] + sred[3] + ibias[ii[b]];
}

// ---------------------------------------------------------------------------
extern "C" void kernel_launch(void* const* d_in, const int* in_sizes, int n_in,
                              void* d_out, int out_size)
{
    const int*   input_u  = (const int*)d_in[0];
    const int*   input_i  = (const int*)d_in[1];
    const int*   input_uf = (const int*)d_in[2];
    const float* uidW     = (const float*)d_in[3];
    const float* iidW     = (const float*)d_in[4];
    const float* i_bias   = (const float*)d_in[5];
    const float* Key      = (const float*)d_in[6];
    const float* Memw     = (const float*)d_in[7];
    const float* WA       = (const float*)d_in[8];
    const float* BA       = (const float*)d_in[9];
    const float* Uo       = (const float*)d_in[10];
    float* out = (float*)d_out;

    int nb = in_sizes[0];
    int user_pad = in_sizes[3] / E - 1;

    float *g_ak_p, *g_mx_p, *g_se_p, *g_mxq_p, *g_seq_p;
    cudaGetSymbolAddress((void**)&g_ak_p, g_ak);
    cudaGetSymbolAddress((void**)&g_mx_p, g_mx);
    cudaGetSymbolAddress((void**)&g_se_p, g_se);
    cudaGetSymbolAddress((void**)&g_mxq_p, g_mxq);
    cudaGetSymbolAddress((void**)&g_seq_p, g_seq);

    const int kmain_smem = (NF*E + NF*E + M*E + FM + 56 + A + A + 8) * 4;
    static int attr_set = 0;
    if (!attr_set) {
        cudaFuncSetAttribute(k_main, cudaFuncAttributeMaxDynamicSharedMemorySize, kmain_smem);
        attr_set = 1;
    }

    k_attkey<<<nb, 256>>>(input_u, input_uf, uidW, Key, g_ak_p, user_pad);
    k_softstats_part<<<dim3(NF, 4), 256>>>(g_ak_p, g_mxq_p, g_seq_p, nb);
    k_softstats_comb<<<1, 512>>>(g_mxq_p, g_seq_p, g_mx_p, g_se_p);
    k_main<<<nb, 256, kmain_smem>>>(input_u, input_i, input_uf, uidW, iidW, i_bias,
                                    Memw, WA, BA, Uo, g_ak_p, g_mx_p, g_se_p, out, user_pad);
}

// round 6
// speedup vs baseline: 1.8787x; 1.4211x over previous
#include <cuda_runtime.h>
#include <cuda_bf16.h>
#include <math_constants.h>
#include <cstdint>

#define B_MAX 4096
#define NF 50
#define E 128
#define A 64
#define M 8
#define FM (NF*M)   // 400

#define FPAD 64          // padded friend rows for mma
#define KP 136           // padded k (bf16 elems) -> 272B row stride
#define HPW 68           // sHP row stride (fp32)

// Scratch (no cudaMalloc allowed)
__device__ float g_ak[B_MAX * FM];
__device__ float g_mx[FM];
__device__ float g_se[FM];
__device__ float g_mxq[4 * FM];
__device__ float g_seq[4 * FM];

__device__ __forceinline__ unsigned int sptr(const void* p) {
    return (unsigned int)__cvta_generic_to_shared(p);
}

#define LDSM_X4(r0, r1, r2, r3, addr) \
    asm volatile("ldmatrix.sync.aligned.m8n8.x4.shared.b16 {%0,%1,%2,%3}, [%4];" \
                 : "=r"(r0), "=r"(r1), "=r"(r2), "=r"(r3) : "r"(addr))
#define LDSM_X2(r0, r1, addr) \
    asm volatile("ldmatrix.sync.aligned.m8n8.x2.shared.b16 {%0,%1}, [%2];" \
                 : "=r"(r0), "=r"(r1) : "r"(addr))
#define MMA16816(c0, c1, c2, c3, a0, a1, a2, a3, b0, b1) \
    asm volatile("mma.sync.aligned.m16n8k16.row.col.f32.bf16.bf16.f32 " \
                 "{%0,%1,%2,%3}, {%4,%5,%6,%7}, {%8,%9}, {%0,%1,%2,%3};" \
                 : "+f"(c0), "+f"(c1), "+f"(c2), "+f"(c3) \
                 : "r"(a0), "r"(a1), "r"(a2), "r"(a3), "r"(b0), "r"(b1))

// ---------------------------------------------------------------------------
// Kernel 1 (unchanged, known-good): att_key via shared staging.
// ---------------------------------------------------------------------------
__global__ __launch_bounds__(256, 4) void k_attkey(
    const int* __restrict__ iu, const int* __restrict__ iuf,
    const float* __restrict__ uidW, const float* __restrict__ Key,
    float* __restrict__ akout, int user_pad)
{
    int b = blockIdx.x;
    int tid = threadIdx.x, lane = tid & 31, warp = tid >> 5;

    __shared__ float sFe[NF][132];
    __shared__ float sKC[M][132];
    __shared__ float sInv[NF + 2];
    __shared__ float sred[8];

    float uv = 0.f;
    if (tid < E) uv = uidW[(size_t)iu[b] * E + tid];
    float p = uv * uv;
    #pragma unroll
    for (int o = 16; o; o >>= 1) p += __shfl_xor_sync(0xffffffffu, p, o);
    if (lane == 0) sred[warp] = p;
    __syncthreads();
    float n2 = 0.f;
    #pragma unroll
    for (int w = 0; w < 8; w++) n2 += sred[w];
    float inv = 1.f / fmaxf(sqrtf(n2), 1e-12f);

    if (tid < E) {
        float un = uv * inv;
        const float4* K4 = (const float4*)(Key + tid * M);
        float4 k0 = K4[0], k1 = K4[1];
        sKC[0][tid] = un * k0.x; sKC[1][tid] = un * k0.y;
        sKC[2][tid] = un * k0.z; sKC[3][tid] = un * k0.w;
        sKC[4][tid] = un * k1.x; sKC[5][tid] = un * k1.y;
        sKC[6][tid] = un * k1.z; sKC[7][tid] = un * k1.w;
    }

    const int* fids = iuf + b * NF;
    for (int f = warp; f < NF; f += 8) {
        int fid = fids[f];
        float fnm = (fid != user_pad) ? 1.f : 0.f;
        float4 v = *(const float4*)(uidW + (size_t)fid * E + lane * 4);
        v.x *= fnm; v.y *= fnm; v.z *= fnm; v.w *= fnm;
        *(float4*)&sFe[f][lane * 4] = v;
    }
    __syncthreads();

    for (int f = warp; f < NF; f += 8) {
        float4 v = *(const float4*)&sFe[f][lane * 4];
        float s = v.x * v.x + v.y * v.y + v.z * v.z + v.w * v.w;
        #pragma unroll
        for (int o = 16; o; o >>= 1) s += __shfl_xor_sync(0xffffffffu, s, o);
        if (lane == 0) sInv[f] = 1.f / fmaxf(sqrtf(s), 1e-12f);
    }
    __syncthreads();

    float* akb = akout + (size_t)b * FM;
    for (int idx = tid; idx < FM; idx += 256) {
        int f = idx >> 3, m = idx & 7;
        const float4* fe4 = (const float4*)sFe[f];
        const float4* kc4 = (const float4*)sKC[m];
        float a0 = 0.f, a1 = 0.f;
        #pragma unroll 4
        for (int e4 = 0; e4 < 32; e4 += 2) {
            float4 x = fe4[e4],     y = kc4[e4];
            a0 = fmaf(x.x, y.x, a0); a0 = fmaf(x.y, y.y, a0);
            a0 = fmaf(x.z, y.z, a0); a0 = fmaf(x.w, y.w, a0);
            float4 x1 = fe4[e4 + 1], y1 = kc4[e4 + 1];
            a1 = fmaf(x1.x, y1.x, a1); a1 = fmaf(x1.y, y1.y, a1);
            a1 = fmaf(x1.z, y1.z, a1); a1 = fmaf(x1.w, y1.w, a1);
        }
        akb[idx] = (a0 + a1) * sInv[f];
    }
}

// ---------------------------------------------------------------------------
// Kernel 2a/2b: split batch-axis softmax stats (unchanged).
// ---------------------------------------------------------------------------
__global__ __launch_bounds__(256) void k_softstats_part(
    const float* __restrict__ ak, float* __restrict__ mxq,
    float* __restrict__ seq, int nb)
{
    int f = blockIdx.x, q = blockIdx.y;
    int b0 = (nb * q) >> 2, b1 = (nb * (q + 1)) >> 2;
    int tid = threadIdx.x, lane = tid & 31, warp = tid >> 5;
    __shared__ float sredm[8][8];
    __shared__ float sreds[8][8];

    float mv[8];
    #pragma unroll
    for (int m = 0; m < 8; m++) mv[m] = -CUDART_INF_F;
    for (int b = b0 + tid; b < b1; b += 256) {
        const float4* p = (const float4*)(ak + (size_t)b * FM + f * 8);
        float4 x0 = p[0], x1 = p[1];
        mv[0] = fmaxf(mv[0], x0.x); mv[1] = fmaxf(mv[1], x0.y);
        mv[2] = fmaxf(mv[2], x0.z); mv[3] = fmaxf(mv[3], x0.w);
        mv[4] = fmaxf(mv[4], x1.x); mv[5] = fmaxf(mv[5], x1.y);
        mv[6] = fmaxf(mv[6], x1.z); mv[7] = fmaxf(mv[7], x1.w);
    }
    #pragma unroll
    for (int m = 0; m < 8; m++) {
        #pragma unroll
        for (int o = 16; o; o >>= 1) mv[m] = fmaxf(mv[m], __shfl_xor_sync(0xffffffffu, mv[m], o));
    }
    if (lane == 0) {
        #pragma unroll
        for (int m = 0; m < 8; m++) sredm[warp][m] = mv[m];
    }
    __syncthreads();
    float mm[8];
    #pragma unroll
    for (int m = 0; m < 8; m++) {
        float v = sredm[0][m];
        #pragma unroll
        for (int w = 1; w < 8; w++) v = fmaxf(v, sredm[w][m]);
        mm[m] = v;
    }

    float sv[8] = {0,0,0,0,0,0,0,0};
    for (int b = b0 + tid; b < b1; b += 256) {
        const float4* p = (const float4*)(ak + (size_t)b * FM + f * 8);
        float4 x0 = p[0], x1 = p[1];
        sv[0] += __expf(x0.x - mm[0]); sv[1] += __expf(x0.y - mm[1]);
        sv[2] += __expf(x0.z - mm[2]); sv[3] += __expf(x0.w - mm[3]);
        sv[4] += __expf(x1.x - mm[4]); sv[5] += __expf(x1.y - mm[5]);
        sv[6] += __expf(x1.z - mm[6]); sv[7] += __expf(x1.w - mm[7]);
    }
    #pragma unroll
    for (int m = 0; m < 8; m++) {
        #pragma unroll
        for (int o = 16; o; o >>= 1) sv[m] += __shfl_xor_sync(0xffffffffu, sv[m], o);
    }
    if (lane == 0) {
        #pragma unroll
        for (int m = 0; m < 8; m++) sreds[warp][m] = sv[m];
    }
    __syncthreads();
    if (tid < 8) {
        float s = 0.f;
        #pragma unroll
        for (int w = 0; w < 8; w++) s += sreds[w][tid];
        mxq[q * FM + f * 8 + tid] = mm[tid];
        seq[q * FM + f * 8 + tid] = s;
    }
}

__global__ __launch_bounds__(512) void k_softstats_comb(
    const float* __restrict__ mxq, const float* __restrict__ seq,
    float* __restrict__ mx, float* __restrict__ se)
{
    int i = threadIdx.x;
    if (i >= FM) return;
    float m0 = mxq[i], m1 = mxq[FM + i], m2 = mxq[2 * FM + i], m3 = mxq[3 * FM + i];
    float mg = fmaxf(fmaxf(m0, m1), fmaxf(m2, m3));
    float s = seq[i] * __expf(m0 - mg) + seq[FM + i] * __expf(m1 - mg)
            + seq[2 * FM + i] * __expf(m2 - mg) + seq[3 * FM + i] * __expf(m3 - mg);
    mx[i] = mg;
    se[i] = s;
}

// ---------------------------------------------------------------------------
// Kernel 3: main pipeline, Phase B on tensor cores (mma.sync bf16).
//   sF2b [64][136] bf16 (rows 50-63 zero) : A operand (f2)
//   sWAT [64][136] bf16 (WA^T)            : B operand
//   C [64f x 64a] -> sHP [64][68] fp32
// ---------------------------------------------------------------------------
__global__ __launch_bounds__(256, 3) void k_main(
    const int* __restrict__ iu, const int* __restrict__ ii,
    const int* __restrict__ iuf, const float* __restrict__ uidW,
    const float* __restrict__ iidW, const float* __restrict__ ibias,
    const float* __restrict__ Memw, const float* __restrict__ WA,
    const float* __restrict__ BA, const float* __restrict__ Uo,
    const float* __restrict__ ak, const float* __restrict__ mx,
    const float* __restrict__ se, float* __restrict__ out, int user_pad)
{
    int b = blockIdx.x, tid = threadIdx.x, lane = tid & 31, warp = tid >> 5;
    int e = tid & 127, g = tid >> 7;

    extern __shared__ char smraw[];
    __nv_bfloat16* sF2b = (__nv_bfloat16*)smraw;                 // 64*136*2 = 17408
    __nv_bfloat16* sWAT = (__nv_bfloat16*)(smraw + 17408);       // 17408
    float* sHP  = (float*)(smraw + 34816);                       // 64*68*4 = 17408
    float* sMem = (float*)(smraw + 52224);                       // 8*128*4 = 4096
    float* sAm  = (float*)(smraw + 56320);                       // 400*4 = 1600
    float* sJ   = (float*)(smraw + 57920);                       // 56*4
    float* sBA  = (float*)(smraw + 58144);                       // 64*4
    float* sUo  = (float*)(smraw + 58400);                       // 64*4
    float* sred = (float*)(smraw + 58656);                       // 8*4

    // --- init loads ---
    for (int i = tid; i < M * E; i += 256) sMem[i] = Memw[i];
    if (tid < A) { sBA[tid] = BA[tid]; sUo[tid] = Uo[tid]; }
    // WA^T -> bf16 (coalesced read of WA[k][n])
    for (int i = tid; i < E * A; i += 256) {
        int k = i >> 6, n = i & 63;
        sWAT[n * KP + k] = __float2bfloat16(WA[i]);
    }
    // zero padded f rows 50..63 of sF2b
    {
        unsigned int* z = (unsigned int*)(sF2b + NF * KP);
        for (int i = tid; i < (FPAD - NF) * KP / 2; i += 256) z[i] = 0u;
    }

    const int* fids = iuf + b * NF;
    const float* akb = ak + (size_t)b * FM;
    for (int i = tid; i < FM; i += 256) {
        int f = i >> 3;
        float fnm = (fids[f] != user_pad) ? 1.f : 0.f;
        sAm[i] = fnm * __expf(akb[i] - mx[i]) / se[i];
    }
    __syncthreads();

    // --- Phase A: f2 (mask folded via sAm) ---
    for (int f = g; f < NF; f += 2) {
        float fe = uidW[(size_t)fids[f] * E + e];
        float f1 = 0.f;
        #pragma unroll
        for (int m = 0; m < M; m++) f1 = fmaf(sAm[f * 8 + m], sMem[m * E + e], f1);
        sF2b[f * KP + e] = __float2bfloat16(f1 * fe);
    }
    __syncthreads();

    // --- Phase B: tensor-core GEMM C[64f][64a] = f2 @ WA ---
    {
        int mt = warp & 3;            // m-tile (16 f rows)
        int ntb = (warp >> 2) * 4;    // first of 4 n-tiles (8 a cols each)
        float c0[4], c1[4], c2[4], c3[4];
        #pragma unroll
        for (int t = 0; t < 4; t++) { c0[t] = c1[t] = c2[t] = c3[t] = 0.f; }

        unsigned int aBase = sptr(sF2b) + (mt * 16 + (lane & 15)) * (KP * 2) + ((lane >> 4) << 4);
        unsigned int bBase = sptr(sWAT) + (lane & 7) * (KP * 2) + (((lane >> 3) & 1) << 4);

        #pragma unroll
        for (int ks = 0; ks < 8; ks++) {
            unsigned int a0, a1, a2, a3;
            LDSM_X4(a0, a1, a2, a3, aBase + ks * 32);
            #pragma unroll
            for (int t = 0; t < 4; t++) {
                unsigned int b0, b1;
                LDSM_X2(b0, b1, bBase + (ntb + t) * 8 * (KP * 2) + ks * 32);
                MMA16816(c0[t], c1[t], c2[t], c3[t], a0, a1, a2, a3, b0, b1);
            }
        }
        int row = mt * 16 + (lane >> 2);
        int col0 = ntb * 8 + (lane & 3) * 2;
        #pragma unroll
        for (int t = 0; t < 4; t++) {
            int col = col0 + t * 8;
            sHP[row * HPW + col]           = c0[t];
            sHP[row * HPW + col + 1]       = c1[t];
            sHP[(row + 8) * HPW + col]     = c2[t];
            sHP[(row + 8) * HPW + col + 1] = c3[t];
        }
    }
    __syncthreads();

    // --- Phase C: j[f] = fn * exp( sum_a relu(h+BA)*Uo ) ---
    for (int f = warp; f < NF; f += 8) {
        float h0 = fmaxf(sHP[f * HPW + lane]      + sBA[lane],      0.f);
        float h1 = fmaxf(sHP[f * HPW + 32 + lane] + sBA[32 + lane], 0.f);
        float jp = h0 * sUo[lane] + h1 * sUo[32 + lane];
        #pragma unroll
        for (int o = 16; o; o >>= 1) jp += __shfl_xor_sync(0xffffffffu, jp, o);
        if (lane == 0) {
            float fnm = (fids[f] != user_pad) ? 1.f : 0.f;
            sJ[f] = fnm * __expf(jp);
        }
    }
    __syncthreads();

    // --- Phase D: weighted friend sum + score ---
    if (tid < 128) {
        float jsum = 0.f;
        #pragma unroll 10
        for (int f = 0; f < NF; f++) jsum += sJ[f];
        float facc = 0.f;
        #pragma unroll 10
        for (int f = 0; f < NF; f++)
            facc = fmaf(sJ[f], __bfloat162float(sF2b[f * KP + e]), facc);
        float user = uidW[(size_t)iu[b] * E + e] + facc / (jsum + 1e-8f);
        int it = ii[b];
        float pp = user * iidW[(size_t)it * E + e];
        #pragma unroll
        for (int o = 16; o; o >>= 1) pp += __shfl_xor_sync(0xffffffffu, pp, o);
        if (lane == 0) sred[warp] = pp;
    }
    __syncthreads();
    if (tid == 0) out[b] = sred[0] + sred[1] + sred[2] + sred[3] + ibias[ii[b]];
}

// ---------------------------------------------------------------------------
extern "C" void kernel_launch(void* const* d_in, const int* in_sizes, int n_in,
                              void* d_out, int out_size)
{
    const int*   input_u  = (const int*)d_in[0];
    const int*   input_i  = (const int*)d_in[1];
    const int*   input_uf = (const int*)d_in[2];
    const float* uidW     = (const float*)d_in[3];
    const float* iidW     = (const float*)d_in[4];
    const float* i_bias   = (const float*)d_in[5];
    const float* Key      = (const float*)d_in[6];
    const float* Memw     = (const float*)d_in[7];
    const float* WA       = (const float*)d_in[8];
    const float* BA       = (const float*)d_in[9];
    const float* Uo       = (const float*)d_in[10];
    float* out = (float*)d_out;

    int nb = in_sizes[0];
    int user_pad = in_sizes[3] / E - 1;

    float *g_ak_p, *g_mx_p, *g_se_p, *g_mxq_p, *g_seq_p;
    cudaGetSymbolAddress((void**)&g_ak_p, g_ak);
    cudaGetSymbolAddress((void**)&g_mx_p, g_mx);
    cudaGetSymbolAddress((void**)&g_se_p, g_se);
    cudaGetSymbolAddress((void**)&g_mxq_p, g_mxq);
    cudaGetSymbolAddress((void**)&g_seq_p, g_seq);

    const int kmain_smem = 58688;
    static int attr_set = 0;
    if (!attr_set) {
        cudaFuncSetAttribute(k_main, cudaFuncAttributeMaxDynamicSharedMemorySize, kmain_smem);
        attr_set = 1;
    }

    k_attkey<<<nb, 256>>>(input_u, input_uf, uidW, Key, g_ak_p, user_pad);
    k_softstats_part<<<dim3(NF, 4), 256>>>(g_ak_p, g_mxq_p, g_seq_p, nb);
    k_softstats_comb<<<1, 512>>>(g_mxq_p, g_seq_p, g_mx_p, g_se_p);
    k_main<<<nb, 256, kmain_smem>>>(input_u, input_i, input_uf, uidW, iidW, i_bias,
                                    Memw, WA, BA, Uo, g_ak_p, g_mx_p, g_se_p, out, user_pad);
}

// round 7
// speedup vs baseline: 2.4176x; 1.2868x over previous
#include <cuda_runtime.h>
#include <cuda_bf16.h>
#include <math_constants.h>
#include <cstdint>

#define B_MAX 4096
#define NF 50
#define E 128
#define A 64
#define M 8
#define FM (NF*M)   // 400

#define FPAD 64          // padded friend rows for mma
#define KP 136           // padded k (bf16 elems) -> 272B row stride
#define HPW 68           // sHP row stride (bf16 elems) -> 136B

// Scratch (no cudaMalloc allowed)
__device__ float g_ak[B_MAX * FM];
__device__ float g_mx[FM];
__device__ float g_se[FM];
__device__ float g_mxq[4 * FM];
__device__ float g_seq[4 * FM];

__device__ __forceinline__ unsigned int sptr(const void* p) {
    return (unsigned int)__cvta_generic_to_shared(p);
}

#define LDSM_X4(r0, r1, r2, r3, addr) \
    asm volatile("ldmatrix.sync.aligned.m8n8.x4.shared.b16 {%0,%1,%2,%3}, [%4];" \
                 : "=r"(r0), "=r"(r1), "=r"(r2), "=r"(r3) : "r"(addr))
#define LDSM_X2(r0, r1, addr) \
    asm volatile("ldmatrix.sync.aligned.m8n8.x2.shared.b16 {%0,%1}, [%2];" \
                 : "=r"(r0), "=r"(r1) : "r"(addr))
#define MMA16816(c0, c1, c2, c3, a0, a1, a2, a3, b0, b1) \
    asm volatile("mma.sync.aligned.m16n8k16.row.col.f32.bf16.bf16.f32 " \
                 "{%0,%1,%2,%3}, {%4,%5,%6,%7}, {%8,%9}, {%0,%1,%2,%3};" \
                 : "+f"(c0), "+f"(c1), "+f"(c2), "+f"(c3) \
                 : "r"(a0), "r"(a1), "r"(a2), "r"(a3), "r"(b0), "r"(b1))

// ---------------------------------------------------------------------------
// Kernel 1 (unchanged, known-good): att_key via shared staging.
// ---------------------------------------------------------------------------
__global__ __launch_bounds__(256, 4) void k_attkey(
    const int* __restrict__ iu, const int* __restrict__ iuf,
    const float* __restrict__ uidW, const float* __restrict__ Key,
    float* __restrict__ akout, int user_pad)
{
    int b = blockIdx.x;
    int tid = threadIdx.x, lane = tid & 31, warp = tid >> 5;

    __shared__ float sFe[NF][132];
    __shared__ float sKC[M][132];
    __shared__ float sInv[NF + 2];
    __shared__ float sred[8];

    float uv = 0.f;
    if (tid < E) uv = uidW[(size_t)iu[b] * E + tid];
    float p = uv * uv;
    #pragma unroll
    for (int o = 16; o; o >>= 1) p += __shfl_xor_sync(0xffffffffu, p, o);
    if (lane == 0) sred[warp] = p;
    __syncthreads();
    float n2 = 0.f;
    #pragma unroll
    for (int w = 0; w < 8; w++) n2 += sred[w];
    float inv = 1.f / fmaxf(sqrtf(n2), 1e-12f);

    if (tid < E) {
        float un = uv * inv;
        const float4* K4 = (const float4*)(Key + tid * M);
        float4 k0 = K4[0], k1 = K4[1];
        sKC[0][tid] = un * k0.x; sKC[1][tid] = un * k0.y;
        sKC[2][tid] = un * k0.z; sKC[3][tid] = un * k0.w;
        sKC[4][tid] = un * k1.x; sKC[5][tid] = un * k1.y;
        sKC[6][tid] = un * k1.z; sKC[7][tid] = un * k1.w;
    }

    const int* fids = iuf + b * NF;
    for (int f = warp; f < NF; f += 8) {
        int fid = fids[f];
        float fnm = (fid != user_pad) ? 1.f : 0.f;
        float4 v = *(const float4*)(uidW + (size_t)fid * E + lane * 4);
        v.x *= fnm; v.y *= fnm; v.z *= fnm; v.w *= fnm;
        *(float4*)&sFe[f][lane * 4] = v;
    }
    __syncthreads();

    for (int f = warp; f < NF; f += 8) {
        float4 v = *(const float4*)&sFe[f][lane * 4];
        float s = v.x * v.x + v.y * v.y + v.z * v.z + v.w * v.w;
        #pragma unroll
        for (int o = 16; o; o >>= 1) s += __shfl_xor_sync(0xffffffffu, s, o);
        if (lane == 0) sInv[f] = 1.f / fmaxf(sqrtf(s), 1e-12f);
    }
    __syncthreads();

    float* akb = akout + (size_t)b * FM;
    for (int idx = tid; idx < FM; idx += 256) {
        int f = idx >> 3, m = idx & 7;
        const float4* fe4 = (const float4*)sFe[f];
        const float4* kc4 = (const float4*)sKC[m];
        float a0 = 0.f, a1 = 0.f;
        #pragma unroll 4
        for (int e4 = 0; e4 < 32; e4 += 2) {
            float4 x = fe4[e4],     y = kc4[e4];
            a0 = fmaf(x.x, y.x, a0); a0 = fmaf(x.y, y.y, a0);
            a0 = fmaf(x.z, y.z, a0); a0 = fmaf(x.w, y.w, a0);
            float4 x1 = fe4[e4 + 1], y1 = kc4[e4 + 1];
            a1 = fmaf(x1.x, y1.x, a1); a1 = fmaf(x1.y, y1.y, a1);
            a1 = fmaf(x1.z, y1.z, a1); a1 = fmaf(x1.w, y1.w, a1);
        }
        akb[idx] = (a0 + a1) * sInv[f];
    }
}

// ---------------------------------------------------------------------------
// Kernel 2a/2b: split batch-axis softmax stats (unchanged).
// ---------------------------------------------------------------------------
__global__ __launch_bounds__(256) void k_softstats_part(
    const float* __restrict__ ak, float* __restrict__ mxq,
    float* __restrict__ seq, int nb)
{
    int f = blockIdx.x, q = blockIdx.y;
    int b0 = (nb * q) >> 2, b1 = (nb * (q + 1)) >> 2;
    int tid = threadIdx.x, lane = tid & 31, warp = tid >> 5;
    __shared__ float sredm[8][8];
    __shared__ float sreds[8][8];

    float mv[8];
    #pragma unroll
    for (int m = 0; m < 8; m++) mv[m] = -CUDART_INF_F;
    for (int b = b0 + tid; b < b1; b += 256) {
        const float4* p = (const float4*)(ak + (size_t)b * FM + f * 8);
        float4 x0 = p[0], x1 = p[1];
        mv[0] = fmaxf(mv[0], x0.x); mv[1] = fmaxf(mv[1], x0.y);
        mv[2] = fmaxf(mv[2], x0.z); mv[3] = fmaxf(mv[3], x0.w);
        mv[4] = fmaxf(mv[4], x1.x); mv[5] = fmaxf(mv[5], x1.y);
        mv[6] = fmaxf(mv[6], x1.z); mv[7] = fmaxf(mv[7], x1.w);
    }
    #pragma unroll
    for (int m = 0; m < 8; m++) {
        #pragma unroll
        for (int o = 16; o; o >>= 1) mv[m] = fmaxf(mv[m], __shfl_xor_sync(0xffffffffu, mv[m], o));
    }
    if (lane == 0) {
        #pragma unroll
        for (int m = 0; m < 8; m++) sredm[warp][m] = mv[m];
    }
    __syncthreads();
    float mm[8];
    #pragma unroll
    for (int m = 0; m < 8; m++) {
        float v = sredm[0][m];
        #pragma unroll
        for (int w = 1; w < 8; w++) v = fmaxf(v, sredm[w][m]);
        mm[m] = v;
    }

    float sv[8] = {0,0,0,0,0,0,0,0};
    for (int b = b0 + tid; b < b1; b += 256) {
        const float4* p = (const float4*)(ak + (size_t)b * FM + f * 8);
        float4 x0 = p[0], x1 = p[1];
        sv[0] += __expf(x0.x - mm[0]); sv[1] += __expf(x0.y - mm[1]);
        sv[2] += __expf(x0.z - mm[2]); sv[3] += __expf(x0.w - mm[3]);
        sv[4] += __expf(x1.x - mm[4]); sv[5] += __expf(x1.y - mm[5]);
        sv[6] += __expf(x1.z - mm[6]); sv[7] += __expf(x1.w - mm[7]);
    }
    #pragma unroll
    for (int m = 0; m < 8; m++) {
        #pragma unroll
        for (int o = 16; o; o >>= 1) sv[m] += __shfl_xor_sync(0xffffffffu, sv[m], o);
    }
    if (lane == 0) {
        #pragma unroll
        for (int m = 0; m < 8; m++) sreds[warp][m] = sv[m];
    }
    __syncthreads();
    if (tid < 8) {
        float s = 0.f;
        #pragma unroll
        for (int w = 0; w < 8; w++) s += sreds[w][tid];
        mxq[q * FM + f * 8 + tid] = mm[tid];
        seq[q * FM + f * 8 + tid] = s;
    }
}

__global__ __launch_bounds__(512) void k_softstats_comb(
    const float* __restrict__ mxq, const float* __restrict__ seq,
    float* __restrict__ mx, float* __restrict__ se)
{
    int i = threadIdx.x;
    if (i >= FM) return;
    float m0 = mxq[i], m1 = mxq[FM + i], m2 = mxq[2 * FM + i], m3 = mxq[3 * FM + i];
    float mg = fmaxf(fmaxf(m0, m1), fmaxf(m2, m3));
    float s = seq[i] * __expf(m0 - mg) + seq[FM + i] * __expf(m1 - mg)
            + seq[2 * FM + i] * __expf(m2 - mg) + seq[3 * FM + i] * __expf(m3 - mg);
    mx[i] = mg;
    se[i] = s;
}

// ---------------------------------------------------------------------------
// Kernel 3: e-pair vectorized main pipeline; Phase B on tensor cores.
// ---------------------------------------------------------------------------
__global__ __launch_bounds__(256, 4) void k_main(
    const int* __restrict__ iu, const int* __restrict__ ii,
    const int* __restrict__ iuf, const float* __restrict__ uidW,
    const float* __restrict__ iidW, const float* __restrict__ ibias,
    const float* __restrict__ Memw, const float* __restrict__ WA,
    const float* __restrict__ BA, const float* __restrict__ Uo,
    const float* __restrict__ ak, const float* __restrict__ mx,
    const float* __restrict__ se, float* __restrict__ out, int user_pad)
{
    int b = blockIdx.x, tid = threadIdx.x, lane = tid & 31, warp = tid >> 5;
    int ep = tid & 63, grp = tid >> 6;       // e-pair id, friend group

    extern __shared__ char smraw[];
    __nv_bfloat16* sF2b = (__nv_bfloat16*)smraw;                 // 64*136*2 = 17408
    __nv_bfloat16* sWAT = (__nv_bfloat16*)(smraw + 17408);       // 17408
    __nv_bfloat16* sHPb = (__nv_bfloat16*)(smraw + 34816);       // 64*68*2 = 8704
    float* sAm  = (float*)(smraw + 43520);                       // 400*4 = 1600
    float* sDP  = (float*)(smraw + 45120);                       // 4*128*4 = 2048
    float* sJ   = (float*)(smraw + 47168);                       // 56*4
    float* sBA2 = (float*)(smraw + 47392);                       // 64*4 (as float2[32])
    float* sUo2 = (float*)(smraw + 47648);                       // 64*4
    float* sred = (float*)(smraw + 47904);                       // 8*4

    // --- init loads ---
    if (tid < A) { sBA2[tid] = BA[tid]; sUo2[tid] = Uo[tid]; }
    // WA^T -> bf16x2 packed along k: thread handles (n, k-pair)
    #pragma unroll
    for (int it = 0; it < 16; it++) {
        int idx = tid + it * 256;
        int n = idx & 63, k = (idx >> 6) * 2;
        __nv_bfloat162 w2 = __floats2bfloat162_rn(WA[k * A + n], WA[(k + 1) * A + n]);
        *(__nv_bfloat162*)&sWAT[n * KP + k] = w2;
    }
    // zero padded f rows 50..63 of sF2b
    {
        unsigned int* z = (unsigned int*)(sF2b + NF * KP);
        for (int i = tid; i < (FPAD - NF) * KP / 2; i += 256) z[i] = 0u;
    }

    const int* fids = iuf + b * NF;
    const float* akb = ak + (size_t)b * FM;
    for (int i = tid; i < FM; i += 256) {
        int f = i >> 3;
        float fnm = (fids[f] != user_pad) ? 1.f : 0.f;
        sAm[i] = fnm * __expf(akb[i] - mx[i]) / se[i];
    }

    // Mem rows for this e-pair -> registers (hoisted out of the f loop)
    float2 mr[8];
    #pragma unroll
    for (int m = 0; m < 8; m++) mr[m] = *(const float2*)(Memw + m * E + ep * 2);
    __syncthreads();

    // --- Phase A: f2 (mask folded via sAm); bf16x2 stores ---
    for (int f = grp; f < NF; f += 4) {
        float2 fe2 = *(const float2*)(uidW + (size_t)fids[f] * E + ep * 2);
        float f1x = 0.f, f1y = 0.f;
        #pragma unroll
        for (int m = 0; m < 8; m++) {
            float am = sAm[f * 8 + m];
            f1x = fmaf(am, mr[m].x, f1x);
            f1y = fmaf(am, mr[m].y, f1y);
        }
        *(__nv_bfloat162*)&sF2b[f * KP + ep * 2] =
            __floats2bfloat162_rn(f1x * fe2.x, f1y * fe2.y);
    }
    __syncthreads();

    // --- Phase B: tensor-core GEMM C[64f][64a] = f2 @ WA ---
    {
        int mt = warp & 3;
        int ntb = (warp >> 2) * 4;
        float c0[4], c1[4], c2[4], c3[4];
        #pragma unroll
        for (int t = 0; t < 4; t++) { c0[t] = c1[t] = c2[t] = c3[t] = 0.f; }

        unsigned int aBase = sptr(sF2b) + (mt * 16 + (lane & 15)) * (KP * 2) + ((lane >> 4) << 4);
        unsigned int bBase = sptr(sWAT) + (lane & 7) * (KP * 2) + (((lane >> 3) & 1) << 4);

        #pragma unroll
        for (int ks = 0; ks < 8; ks++) {
            unsigned int a0, a1, a2, a3;
            LDSM_X4(a0, a1, a2, a3, aBase + ks * 32);
            #pragma unroll
            for (int t = 0; t < 4; t++) {
                unsigned int b0, b1;
                LDSM_X2(b0, b1, bBase + (ntb + t) * 8 * (KP * 2) + ks * 32);
                MMA16816(c0[t], c1[t], c2[t], c3[t], a0, a1, a2, a3, b0, b1);
            }
        }
        int row = mt * 16 + (lane >> 2);
        int col0 = ntb * 8 + (lane & 3) * 2;
        #pragma unroll
        for (int t = 0; t < 4; t++) {
            int col = col0 + t * 8;
            *(__nv_bfloat162*)&sHPb[row * HPW + col] = __floats2bfloat162_rn(c0[t], c1[t]);
            *(__nv_bfloat162*)&sHPb[(row + 8) * HPW + col] = __floats2bfloat162_rn(c2[t], c3[t]);
        }
    }
    __syncthreads();

    // --- Phase C: j[f] = fn * exp( sum_a relu(h+BA)*Uo ); lane owns a-pair ---
    for (int f = warp; f < NF; f += 8) {
        float2 h2 = __bfloat1622float2(*(const __nv_bfloat162*)&sHPb[f * HPW + lane * 2]);
        float2 ba = *(const float2*)&sBA2[lane * 2];
        float2 uo = *(const float2*)&sUo2[lane * 2];
        float jp = fmaxf(h2.x + ba.x, 0.f) * uo.x + fmaxf(h2.y + ba.y, 0.f) * uo.y;
        #pragma unroll
        for (int o = 16; o; o >>= 1) jp += __shfl_xor_sync(0xffffffffu, jp, o);
        if (lane == 0) {
            float fnm = (fids[f] != user_pad) ? 1.f : 0.f;
            sJ[f] = fnm * __expf(jp);
        }
    }
    __syncthreads();

    // --- Phase D: weighted friend sum (partials per group), then score ---
    {
        float px = 0.f, py = 0.f;
        for (int f = grp; f < NF; f += 4) {
            float jw = sJ[f];
            float2 f2v = __bfloat1622float2(*(const __nv_bfloat162*)&sF2b[f * KP + ep * 2]);
            px = fmaf(jw, f2v.x, px);
            py = fmaf(jw, f2v.y, py);
        }
        sDP[grp * 128 + ep * 2]     = px;
        sDP[grp * 128 + ep * 2 + 1] = py;
    }
    __syncthreads();

    if (tid < 128) {
        int e = tid;
        float jsum = 0.f;
        #pragma unroll 10
        for (int f = 0; f < NF; f++) jsum += sJ[f];
        float facc = sDP[e] + sDP[128 + e] + sDP[256 + e] + sDP[384 + e];
        float user = uidW[(size_t)iu[b] * E + e] + facc / (jsum + 1e-8f);
        int it = ii[b];
        float pp = user * iidW[(size_t)it * E + e];
        #pragma unroll
        for (int o = 16; o; o >>= 1) pp += __shfl_xor_sync(0xffffffffu, pp, o);
        if (lane == 0) sred[warp] = pp;
    }
    __syncthreads();
    if (tid == 0) out[b] = sred[0] + sred[1] + sred[2] + sred[3] + ibias[ii[b]];
}

// ---------------------------------------------------------------------------
extern "C" void kernel_launch(void* const* d_in, const int* in_sizes, int n_in,
                              void* d_out, int out_size)
{
    const int*   input_u  = (const int*)d_in[0];
    const int*   input_i  = (const int*)d_in[1];
    const int*   input_uf = (const int*)d_in[2];
    const float* uidW     = (const float*)d_in[3];
    const float* iidW     = (const float*)d_in[4];
    const float* i_bias   = (const float*)d_in[5];
    const float* Key      = (const float*)d_in[6];
    const float* Memw     = (const float*)d_in[7];
    const float* WA       = (const float*)d_in[8];
    const float* BA       = (const float*)d_in[9];
    const float* Uo       = (const float*)d_in[10];
    float* out = (float*)d_out;

    int nb = in_sizes[0];
    int user_pad = in_sizes[3] / E - 1;

    float *g_ak_p, *g_mx_p, *g_se_p, *g_mxq_p, *g_seq_p;
    cudaGetSymbolAddress((void**)&g_ak_p, g_ak);
    cudaGetSymbolAddress((void**)&g_mx_p, g_mx);
    cudaGetSymbolAddress((void**)&g_se_p, g_se);
    cudaGetSymbolAddress((void**)&g_mxq_p, g_mxq);
    cudaGetSymbolAddress((void**)&g_seq_p, g_seq);

    const int kmain_smem = 47936;
    static int attr_set = 0;
    if (!attr_set) {
        cudaFuncSetAttribute(k_main, cudaFuncAttributeMaxDynamicSharedMemorySize, kmain_smem);
        attr_set = 1;
    }

    k_attkey<<<nb, 256>>>(input_u, input_uf, uidW, Key, g_ak_p, user_pad);
    k_softstats_part<<<dim3(NF, 4), 256>>>(g_ak_p, g_mxq_p, g_seq_p, nb);
    k_softstats_comb<<<1, 512>>>(g_mxq_p, g_seq_p, g_mx_p, g_se_p);
    k_main<<<nb, 256, kmain_smem>>>(input_u, input_i, input_uf, uidW, iidW, i_bias,
                                    Memw, WA, BA, Uo, g_ak_p, g_mx_p, g_se_p, out, user_pad);
}

// round 8
// speedup vs baseline: 3.2255x; 1.3342x over previous
#include <cuda_runtime.h>
#include <cuda_bf16.h>
#include <math_constants.h>
#include <cstdint>

#define B_MAX 4096
#define NF 50
#define E 128
#define A 64
#define M 8
#define FM (NF*M)   // 400

#define FPAD 64          // padded friend rows for mma
#define KP 136           // padded k (bf16 elems) -> 272B row stride
#define HPW 68           // sHP row stride (bf16 elems)

// Scratch (no cudaMalloc allowed)
__device__ float g_ak[B_MAX * FM];
__device__ float g_mx[FM];
__device__ float g_se[FM];
__device__ float g_mxq[4 * FM];
__device__ float g_seq[4 * FM];

__device__ __forceinline__ unsigned int sptr(const void* p) {
    return (unsigned int)__cvta_generic_to_shared(p);
}

#define LDSM_X4(r0, r1, r2, r3, addr) \
    asm volatile("ldmatrix.sync.aligned.m8n8.x4.shared.b16 {%0,%1,%2,%3}, [%4];" \
                 : "=r"(r0), "=r"(r1), "=r"(r2), "=r"(r3) : "r"(addr))
#define LDSM_X2(r0, r1, addr) \
    asm volatile("ldmatrix.sync.aligned.m8n8.x2.shared.b16 {%0,%1}, [%2];" \
                 : "=r"(r0), "=r"(r1) : "r"(addr))
#define MMA16816(c0, c1, c2, c3, a0, a1, a2, a3, b0, b1) \
    asm volatile("mma.sync.aligned.m16n8k16.row.col.f32.bf16.bf16.f32 " \
                 "{%0,%1,%2,%3}, {%4,%5,%6,%7}, {%8,%9}, {%0,%1,%2,%3};" \
                 : "+f"(c0), "+f"(c1), "+f"(c2), "+f"(c3) \
                 : "r"(a0), "r"(a1), "r"(a2), "r"(a3), "r"(b0), "r"(b1))

// ---------------------------------------------------------------------------
// Kernel 1: att_key on tensor cores.
//   sFeb [64][136] bf16 : fe_n (masked, normalized) rows, 50-63 zero
//   sKCT [8][136]  bf16 : (uid_n ⊙ Key)^T
//   C [64f x 8m] via 4 m-tiles x 2 k-half warps, partials summed in smem.
// ---------------------------------------------------------------------------
__global__ __launch_bounds__(256, 4) void k_attkey(
    const int* __restrict__ iu, const int* __restrict__ iuf,
    const float* __restrict__ uidW, const float* __restrict__ Key,
    float* __restrict__ akout, int user_pad)
{
    int b = blockIdx.x;
    int tid = threadIdx.x, lane = tid & 31, warp = tid >> 5;

    __shared__ __nv_bfloat16 sFeb[FPAD * KP];   // 17408 B
    __shared__ __nv_bfloat16 sKCT[M * KP];      // 2176 B
    __shared__ float sC[2][FPAD * M];           // 4096 B
    __shared__ float sred[8];

    // uid l2 norm
    float uv = 0.f;
    if (tid < E) uv = uidW[(size_t)iu[b] * E + tid];
    float p = uv * uv;
    #pragma unroll
    for (int o = 16; o; o >>= 1) p += __shfl_xor_sync(0xffffffffu, p, o);
    if (lane == 0) sred[warp] = p;
    __syncthreads();
    float n2 = 0.f;
    #pragma unroll
    for (int w = 0; w < 8; w++) n2 += sred[w];
    float inv = 1.f / fmaxf(sqrtf(n2), 1e-12f);

    // kc^T = (uid_n * Key)^T -> bf16
    if (tid < E) {
        float un = uv * inv;
        const float4* K4 = (const float4*)(Key + tid * M);
        float4 k0 = K4[0], k1 = K4[1];
        sKCT[0 * KP + tid] = __float2bfloat16(un * k0.x);
        sKCT[1 * KP + tid] = __float2bfloat16(un * k0.y);
        sKCT[2 * KP + tid] = __float2bfloat16(un * k0.z);
        sKCT[3 * KP + tid] = __float2bfloat16(un * k0.w);
        sKCT[4 * KP + tid] = __float2bfloat16(un * k1.x);
        sKCT[5 * KP + tid] = __float2bfloat16(un * k1.y);
        sKCT[6 * KP + tid] = __float2bfloat16(un * k1.z);
        sKCT[7 * KP + tid] = __float2bfloat16(un * k1.w);
    }

    // zero padded rows 50..63 of sFeb
    {
        unsigned int* z = (unsigned int*)(sFeb + NF * KP);
        for (int i = tid; i < (FPAD - NF) * KP / 2; i += 256) z[i] = 0u;
    }

    // stage fe_n rows: warp per f; mask + normalize in one pass
    const int* fids = iuf + b * NF;
    for (int f = warp; f < NF; f += 8) {
        int fid = fids[f];
        float fnm = (fid != user_pad) ? 1.f : 0.f;
        float4 v = *(const float4*)(uidW + (size_t)fid * E + lane * 4);
        v.x *= fnm; v.y *= fnm; v.z *= fnm; v.w *= fnm;
        float s = v.x * v.x + v.y * v.y + v.z * v.z + v.w * v.w;
        #pragma unroll
        for (int o = 16; o; o >>= 1) s += __shfl_xor_sync(0xffffffffu, s, o);
        float invf = 1.f / fmaxf(sqrtf(s), 1e-12f);
        __nv_bfloat162 p0 = __floats2bfloat162_rn(v.x * invf, v.y * invf);
        __nv_bfloat162 p1 = __floats2bfloat162_rn(v.z * invf, v.w * invf);
        *(__nv_bfloat162*)&sFeb[f * KP + lane * 4]     = p0;
        *(__nv_bfloat162*)&sFeb[f * KP + lane * 4 + 2] = p1;
    }
    __syncthreads();

    // GEMM C[64f][8m] = fe_n @ kc ; warp = (m-tile, k-half)
    {
        int mt = warp & 3, kh = warp >> 2;
        float c0 = 0.f, c1 = 0.f, c2 = 0.f, c3 = 0.f;
        unsigned int aBase = sptr(sFeb) + (mt * 16 + (lane & 15)) * (KP * 2)
                           + ((lane >> 4) << 4) + kh * 128;
        unsigned int bBase = sptr(sKCT) + (lane & 7) * (KP * 2)
                           + (((lane >> 3) & 1) << 4) + kh * 128;
        #pragma unroll
        for (int ks = 0; ks < 4; ks++) {
            unsigned int a0, a1, a2, a3, b0, b1;
            LDSM_X4(a0, a1, a2, a3, aBase + ks * 32);
            LDSM_X2(b0, b1, bBase + ks * 32);
            MMA16816(c0, c1, c2, c3, a0, a1, a2, a3, b0, b1);
        }
        int row = mt * 16 + (lane >> 2);
        int col = (lane & 3) * 2;
        sC[kh][row * M + col]           = c0;
        sC[kh][row * M + col + 1]       = c1;
        sC[kh][(row + 8) * M + col]     = c2;
        sC[kh][(row + 8) * M + col + 1] = c3;
    }
    __syncthreads();

    // combine k-half partials, coalesced fp32 write
    float* akb = akout + (size_t)b * FM;
    for (int idx = tid; idx < FM; idx += 256)
        akb[idx] = sC[0][idx] + sC[1][idx];
}

// ---------------------------------------------------------------------------
// Kernel 2a/2b: split batch-axis softmax stats (unchanged).
// ---------------------------------------------------------------------------
__global__ __launch_bounds__(256) void k_softstats_part(
    const float* __restrict__ ak, float* __restrict__ mxq,
    float* __restrict__ seq, int nb)
{
    int f = blockIdx.x, q = blockIdx.y;
    int b0 = (nb * q) >> 2, b1 = (nb * (q + 1)) >> 2;
    int tid = threadIdx.x, lane = tid & 31, warp = tid >> 5;
    __shared__ float sredm[8][8];
    __shared__ float sreds[8][8];

    float mv[8];
    #pragma unroll
    for (int m = 0; m < 8; m++) mv[m] = -CUDART_INF_F;
    for (int b = b0 + tid; b < b1; b += 256) {
        const float4* p = (const float4*)(ak + (size_t)b * FM + f * 8);
        float4 x0 = p[0], x1 = p[1];
        mv[0] = fmaxf(mv[0], x0.x); mv[1] = fmaxf(mv[1], x0.y);
        mv[2] = fmaxf(mv[2], x0.z); mv[3] = fmaxf(mv[3], x0.w);
        mv[4] = fmaxf(mv[4], x1.x); mv[5] = fmaxf(mv[5], x1.y);
        mv[6] = fmaxf(mv[6], x1.z); mv[7] = fmaxf(mv[7], x1.w);
    }
    #pragma unroll
    for (int m = 0; m < 8; m++) {
        #pragma unroll
        for (int o = 16; o; o >>= 1) mv[m] = fmaxf(mv[m], __shfl_xor_sync(0xffffffffu, mv[m], o));
    }
    if (lane == 0) {
        #pragma unroll
        for (int m = 0; m < 8; m++) sredm[warp][m] = mv[m];
    }
    __syncthreads();
    float mm[8];
    #pragma unroll
    for (int m = 0; m < 8; m++) {
        float v = sredm[0][m];
        #pragma unroll
        for (int w = 1; w < 8; w++) v = fmaxf(v, sredm[w][m]);
        mm[m] = v;
    }

    float sv[8] = {0,0,0,0,0,0,0,0};
    for (int b = b0 + tid; b < b1; b += 256) {
        const float4* p = (const float4*)(ak + (size_t)b * FM + f * 8);
        float4 x0 = p[0], x1 = p[1];
        sv[0] += __expf(x0.x - mm[0]); sv[1] += __expf(x0.y - mm[1]);
        sv[2] += __expf(x0.z - mm[2]); sv[3] += __expf(x0.w - mm[3]);
        sv[4] += __expf(x1.x - mm[4]); sv[5] += __expf(x1.y - mm[5]);
        sv[6] += __expf(x1.z - mm[6]); sv[7] += __expf(x1.w - mm[7]);
    }
    #pragma unroll
    for (int m = 0; m < 8; m++) {
        #pragma unroll
        for (int o = 16; o; o >>= 1) sv[m] += __shfl_xor_sync(0xffffffffu, sv[m], o);
    }
    if (lane == 0) {
        #pragma unroll
        for (int m = 0; m < 8; m++) sreds[warp][m] = sv[m];
    }
    __syncthreads();
    if (tid < 8) {
        float s = 0.f;
        #pragma unroll
        for (int w = 0; w < 8; w++) s += sreds[w][tid];
        mxq[q * FM + f * 8 + tid] = mm[tid];
        seq[q * FM + f * 8 + tid] = s;
    }
}

__global__ __launch_bounds__(512) void k_softstats_comb(
    const float* __restrict__ mxq, const float* __restrict__ seq,
    float* __restrict__ mx, float* __restrict__ se)
{
    int i = threadIdx.x;
    if (i >= FM) return;
    float m0 = mxq[i], m1 = mxq[FM + i], m2 = mxq[2 * FM + i], m3 = mxq[3 * FM + i];
    float mg = fmaxf(fmaxf(m0, m1), fmaxf(m2, m3));
    float s = seq[i] * __expf(m0 - mg) + seq[FM + i] * __expf(m1 - mg)
            + seq[2 * FM + i] * __expf(m2 - mg) + seq[3 * FM + i] * __expf(m3 - mg);
    mx[i] = mg;
    se[i] = s;
}

// ---------------------------------------------------------------------------
// Kernel 3: e-pair vectorized main pipeline; Phase B on tensor cores
// (unchanged from R7 — known good).
// ---------------------------------------------------------------------------
__global__ __launch_bounds__(256, 4) void k_main(
    const int* __restrict__ iu, const int* __restrict__ ii,
    const int* __restrict__ iuf, const float* __restrict__ uidW,
    const float* __restrict__ iidW, const float* __restrict__ ibias,
    const float* __restrict__ Memw, const float* __restrict__ WA,
    const float* __restrict__ BA, const float* __restrict__ Uo,
    const float* __restrict__ ak, const float* __restrict__ mx,
    const float* __restrict__ se, float* __restrict__ out, int user_pad)
{
    int b = blockIdx.x, tid = threadIdx.x, lane = tid & 31, warp = tid >> 5;
    int ep = tid & 63, grp = tid >> 6;

    extern __shared__ char smraw[];
    __nv_bfloat16* sF2b = (__nv_bfloat16*)smraw;                 // 17408
    __nv_bfloat16* sWAT = (__nv_bfloat16*)(smraw + 17408);       // 17408
    __nv_bfloat16* sHPb = (__nv_bfloat16*)(smraw + 34816);       // 8704
    float* sAm  = (float*)(smraw + 43520);                       // 1600
    float* sDP  = (float*)(smraw + 45120);                       // 2048
    float* sJ   = (float*)(smraw + 47168);                       // 224
    float* sBA2 = (float*)(smraw + 47392);                       // 256
    float* sUo2 = (float*)(smraw + 47648);                       // 256
    float* sred = (float*)(smraw + 47904);                       // 32

    if (tid < A) { sBA2[tid] = BA[tid]; sUo2[tid] = Uo[tid]; }
    #pragma unroll
    for (int it = 0; it < 16; it++) {
        int idx = tid + it * 256;
        int n = idx & 63, k = (idx >> 6) * 2;
        __nv_bfloat162 w2 = __floats2bfloat162_rn(WA[k * A + n], WA[(k + 1) * A + n]);
        *(__nv_bfloat162*)&sWAT[n * KP + k] = w2;
    }
    {
        unsigned int* z = (unsigned int*)(sF2b + NF * KP);
        for (int i = tid; i < (FPAD - NF) * KP / 2; i += 256) z[i] = 0u;
    }

    const int* fids = iuf + b * NF;
    const float* akb = ak + (size_t)b * FM;
    for (int i = tid; i < FM; i += 256) {
        int f = i >> 3;
        float fnm = (fids[f] != user_pad) ? 1.f : 0.f;
        sAm[i] = fnm * __expf(akb[i] - mx[i]) / se[i];
    }

    float2 mr[8];
    #pragma unroll
    for (int m = 0; m < 8; m++) mr[m] = *(const float2*)(Memw + m * E + ep * 2);
    __syncthreads();

    for (int f = grp; f < NF; f += 4) {
        float2 fe2 = *(const float2*)(uidW + (size_t)fids[f] * E + ep * 2);
        float f1x = 0.f, f1y = 0.f;
        #pragma unroll
        for (int m = 0; m < 8; m++) {
            float am = sAm[f * 8 + m];
            f1x = fmaf(am, mr[m].x, f1x);
            f1y = fmaf(am, mr[m].y, f1y);
        }
        *(__nv_bfloat162*)&sF2b[f * KP + ep * 2] =
            __floats2bfloat162_rn(f1x * fe2.x, f1y * fe2.y);
    }
    __syncthreads();

    {
        int mt = warp & 3;
        int ntb = (warp >> 2) * 4;
        float c0[4], c1[4], c2[4], c3[4];
        #pragma unroll
        for (int t = 0; t < 4; t++) { c0[t] = c1[t] = c2[t] = c3[t] = 0.f; }

        unsigned int aBase = sptr(sF2b) + (mt * 16 + (lane & 15)) * (KP * 2) + ((lane >> 4) << 4);
        unsigned int bBase = sptr(sWAT) + (lane & 7) * (KP * 2) + (((lane >> 3) & 1) << 4);

        #pragma unroll
        for (int ks = 0; ks < 8; ks++) {
            unsigned int a0, a1, a2, a3;
            LDSM_X4(a0, a1, a2, a3, aBase + ks * 32);
            #pragma unroll
            for (int t = 0; t < 4; t++) {
                unsigned int b0, b1;
                LDSM_X2(b0, b1, bBase + (ntb + t) * 8 * (KP * 2) + ks * 32);
                MMA16816(c0[t], c1[t], c2[t], c3[t], a0, a1, a2, a3, b0, b1);
            }
        }
        int row = mt * 16 + (lane >> 2);
        int col0 = ntb * 8 + (lane & 3) * 2;
        #pragma unroll
        for (int t = 0; t < 4; t++) {
            int col = col0 + t * 8;
            *(__nv_bfloat162*)&sHPb[row * HPW + col] = __floats2bfloat162_rn(c0[t], c1[t]);
            *(__nv_bfloat162*)&sHPb[(row + 8) * HPW + col] = __floats2bfloat162_rn(c2[t], c3[t]);
        }
    }
    __syncthreads();

    for (int f = warp; f < NF; f += 8) {
        float2 h2 = __bfloat1622float2(*(const __nv_bfloat162*)&sHPb[f * HPW + lane * 2]);
        float2 ba = *(const float2*)&sBA2[lane * 2];
        float2 uo = *(const float2*)&sUo2[lane * 2];
        float jp = fmaxf(h2.x + ba.x, 0.f) * uo.x + fmaxf(h2.y + ba.y, 0.f) * uo.y;
        #pragma unroll
        for (int o = 16; o; o >>= 1) jp += __shfl_xor_sync(0xffffffffu, jp, o);
        if (lane == 0) {
            float fnm = (fids[f] != user_pad) ? 1.f : 0.f;
            sJ[f] = fnm * __expf(jp);
        }
    }
    __syncthreads();

    {
        float px = 0.f, py = 0.f;
        for (int f = grp; f < NF; f += 4) {
            float jw = sJ[f];
            float2 f2v = __bfloat1622float2(*(const __nv_bfloat162*)&sF2b[f * KP + ep * 2]);
            px = fmaf(jw, f2v.x, px);
            py = fmaf(jw, f2v.y, py);
        }
        sDP[grp * 128 + ep * 2]     = px;
        sDP[grp * 128 + ep * 2 + 1] = py;
    }
    __syncthreads();

    if (tid < 128) {
        int e = tid;
        float jsum = 0.f;
        #pragma unroll 10
        for (int f = 0; f < NF; f++) jsum += sJ[f];
        float facc = sDP[e] + sDP[128 + e] + sDP[256 + e] + sDP[384 + e];
        float user = uidW[(size_t)iu[b] * E + e] + facc / (jsum + 1e-8f);
        int it = ii[b];
        float pp = user * iidW[(size_t)it * E + e];
        #pragma unroll
        for (int o = 16; o; o >>= 1) pp += __shfl_xor_sync(0xffffffffu, pp, o);
        if (lane == 0) sred[warp] = pp;
    }
    __syncthreads();
    if (tid == 0) out[b] = sred[0] + sred[1] + sred[2] + sred[3] + ibias[ii[b]];
}

// ---------------------------------------------------------------------------
extern "C" void kernel_launch(void* const* d_in, const int* in_sizes, int n_in,
                              void* d_out, int out_size)
{
    const int*   input_u  = (const int*)d_in[0];
    const int*   input_i  = (const int*)d_in[1];
    const int*   input_uf = (const int*)d_in[2];
    const float* uidW     = (const float*)d_in[3];
    const float* iidW     = (const float*)d_in[4];
    const float* i_bias   = (const float*)d_in[5];
    const float* Key      = (const float*)d_in[6];
    const float* Memw     = (const float*)d_in[7];
    const float* WA       = (const float*)d_in[8];
    const float* BA       = (const float*)d_in[9];
    const float* Uo       = (const float*)d_in[10];
    float* out = (float*)d_out;

    int nb = in_sizes[0];
    int user_pad = in_sizes[3] / E - 1;

    float *g_ak_p, *g_mx_p, *g_se_p, *g_mxq_p, *g_seq_p;
    cudaGetSymbolAddress((void**)&g_ak_p, g_ak);
    cudaGetSymbolAddress((void**)&g_mx_p, g_mx);
    cudaGetSymbolAddress((void**)&g_se_p, g_se);
    cudaGetSymbolAddress((void**)&g_mxq_p, g_mxq);
    cudaGetSymbolAddress((void**)&g_seq_p, g_seq);

    const int kmain_smem = 47936;
    static int attr_set = 0;
    if (!attr_set) {
        cudaFuncSetAttribute(k_main, cudaFuncAttributeMaxDynamicSharedMemorySize, kmain_smem);
        attr_set = 1;
    }

    k_attkey<<<nb, 256>>>(input_u, input_uf, uidW, Key, g_ak_p, user_pad);
    k_softstats_part<<<dim3(NF, 4), 256>>>(g_ak_p, g_mxq_p, g_seq_p, nb);
    k_softstats_comb<<<1, 512>>>(g_mxq_p, g_seq_p, g_mx_p, g_se_p);
    k_main<<<nb, 256, kmain_smem>>>(input_u, input_i, input_uf, uidW, iidW, i_bias,
                                    Memw, WA, BA, Uo, g_ak_p, g_mx_p, g_se_p, out, user_pad);
}

// round 9
// speedup vs baseline: 3.6523x; 1.1323x over previous
#include <cuda_runtime.h>
#include <cuda_bf16.h>
#include <math_constants.h>
#include <cstdint>

#define B_MAX 4096
#define NF 50
#define E 128
#define A 64
#define M 8
#define FM (NF*M)   // 400

#define FPAD 64          // padded friend rows for mma
#define KP 136           // padded k (bf16 elems) -> 272B row stride
#define HPW 68           // sHP row stride (bf16 elems)

// Scratch (no cudaMalloc allowed)
__device__ float g_ak[B_MAX * FM];
__device__ float g_mx[FM];
__device__ float g_se[FM];
__device__ float g_mxq[4 * FM];
__device__ float g_seq[4 * FM];

__device__ __forceinline__ unsigned int sptr(const void* p) {
    return (unsigned int)__cvta_generic_to_shared(p);
}

#define LDSM_X4(r0, r1, r2, r3, addr) \
    asm volatile("ldmatrix.sync.aligned.m8n8.x4.shared.b16 {%0,%1,%2,%3}, [%4];" \
                 : "=r"(r0), "=r"(r1), "=r"(r2), "=r"(r3) : "r"(addr))
#define LDSM_X2(r0, r1, addr) \
    asm volatile("ldmatrix.sync.aligned.m8n8.x2.shared.b16 {%0,%1}, [%2];" \
                 : "=r"(r0), "=r"(r1) : "r"(addr))
#define MMA16816(c0, c1, c2, c3, a0, a1, a2, a3, b0, b1) \
    asm volatile("mma.sync.aligned.m16n8k16.row.col.f32.bf16.bf16.f32 " \
                 "{%0,%1,%2,%3}, {%4,%5,%6,%7}, {%8,%9}, {%0,%1,%2,%3};" \
                 : "+f"(c0), "+f"(c1), "+f"(c2), "+f"(c3) \
                 : "r"(a0), "r"(a1), "r"(a2), "r"(a3), "r"(b0), "r"(b1))

// ---------------------------------------------------------------------------
// Kernel 1: att_key on tensor cores (junk padded rows never read -> no zfill).
// ---------------------------------------------------------------------------
__global__ __launch_bounds__(256, 4) void k_attkey(
    const int* __restrict__ iu, const int* __restrict__ iuf,
    const float* __restrict__ uidW, const float* __restrict__ Key,
    float* __restrict__ akout, int user_pad)
{
    int b = blockIdx.x;
    int tid = threadIdx.x, lane = tid & 31, warp = tid >> 5;

    __shared__ __nv_bfloat16 sFeb[FPAD * KP];   // 17408 B
    __shared__ __nv_bfloat16 sKCT[M * KP];      // 2176 B
    __shared__ float sC[2][FPAD * M];           // 4096 B
    __shared__ float sred[8];

    // uid l2 norm
    float uv = 0.f;
    if (tid < E) uv = uidW[(size_t)iu[b] * E + tid];
    float p = uv * uv;
    #pragma unroll
    for (int o = 16; o; o >>= 1) p += __shfl_xor_sync(0xffffffffu, p, o);
    if (lane == 0) sred[warp] = p;
    __syncthreads();
    float n2 = 0.f;
    #pragma unroll
    for (int w = 0; w < 8; w++) n2 += sred[w];
    float inv = 1.f / fmaxf(sqrtf(n2), 1e-12f);

    // kc^T = (uid_n * Key)^T -> bf16
    if (tid < E) {
        float un = uv * inv;
        const float4* K4 = (const float4*)(Key + tid * M);
        float4 k0 = K4[0], k1 = K4[1];
        sKCT[0 * KP + tid] = __float2bfloat16(un * k0.x);
        sKCT[1 * KP + tid] = __float2bfloat16(un * k0.y);
        sKCT[2 * KP + tid] = __float2bfloat16(un * k0.z);
        sKCT[3 * KP + tid] = __float2bfloat16(un * k0.w);
        sKCT[4 * KP + tid] = __float2bfloat16(un * k1.x);
        sKCT[5 * KP + tid] = __float2bfloat16(un * k1.y);
        sKCT[6 * KP + tid] = __float2bfloat16(un * k1.z);
        sKCT[7 * KP + tid] = __float2bfloat16(un * k1.w);
    }

    // stage fe_n rows: warp per f; mask + normalize in one pass
    const int* fids = iuf + b * NF;
    for (int f = warp; f < NF; f += 8) {
        int fid = fids[f];
        float fnm = (fid != user_pad) ? 1.f : 0.f;
        float4 v = *(const float4*)(uidW + (size_t)fid * E + lane * 4);
        v.x *= fnm; v.y *= fnm; v.z *= fnm; v.w *= fnm;
        float s = v.x * v.x + v.y * v.y + v.z * v.z + v.w * v.w;
        #pragma unroll
        for (int o = 16; o; o >>= 1) s += __shfl_xor_sync(0xffffffffu, s, o);
        float invf = 1.f / fmaxf(sqrtf(s), 1e-12f);
        __nv_bfloat162 p0 = __floats2bfloat162_rn(v.x * invf, v.y * invf);
        __nv_bfloat162 p1 = __floats2bfloat162_rn(v.z * invf, v.w * invf);
        *(__nv_bfloat162*)&sFeb[f * KP + lane * 4]     = p0;
        *(__nv_bfloat162*)&sFeb[f * KP + lane * 4 + 2] = p1;
    }
    __syncthreads();

    // GEMM C[64f][8m] = fe_n @ kc ; warp = (m-tile, k-half)
    {
        int mt = warp & 3, kh = warp >> 2;
        float c0 = 0.f, c1 = 0.f, c2 = 0.f, c3 = 0.f;
        unsigned int aBase = sptr(sFeb) + (mt * 16 + (lane & 15)) * (KP * 2)
                           + ((lane >> 4) << 4) + kh * 128;
        unsigned int bBase = sptr(sKCT) + (lane & 7) * (KP * 2)
                           + (((lane >> 3) & 1) << 4) + kh * 128;
        #pragma unroll
        for (int ks = 0; ks < 4; ks++) {
            unsigned int a0, a1, a2, a3, b0, b1;
            LDSM_X4(a0, a1, a2, a3, aBase + ks * 32);
            LDSM_X2(b0, b1, bBase + ks * 32);
            MMA16816(c0, c1, c2, c3, a0, a1, a2, a3, b0, b1);
        }
        int row = mt * 16 + (lane >> 2);
        int col = (lane & 3) * 2;
        sC[kh][row * M + col]           = c0;
        sC[kh][row * M + col + 1]       = c1;
        sC[kh][(row + 8) * M + col]     = c2;
        sC[kh][(row + 8) * M + col + 1] = c3;
    }
    __syncthreads();

    float* akb = akout + (size_t)b * FM;
    for (int idx = tid; idx < FM; idx += 256)
        akb[idx] = sC[0][idx] + sC[1][idx];
}

// ---------------------------------------------------------------------------
// Kernel 2a/2b: split batch-axis softmax stats (unchanged).
// ---------------------------------------------------------------------------
__global__ __launch_bounds__(256) void k_softstats_part(
    const float* __restrict__ ak, float* __restrict__ mxq,
    float* __restrict__ seq, int nb)
{
    int f = blockIdx.x, q = blockIdx.y;
    int b0 = (nb * q) >> 2, b1 = (nb * (q + 1)) >> 2;
    int tid = threadIdx.x, lane = tid & 31, warp = tid >> 5;
    __shared__ float sredm[8][8];
    __shared__ float sreds[8][8];

    float mv[8];
    #pragma unroll
    for (int m = 0; m < 8; m++) mv[m] = -CUDART_INF_F;
    for (int b = b0 + tid; b < b1; b += 256) {
        const float4* p = (const float4*)(ak + (size_t)b * FM + f * 8);
        float4 x0 = p[0], x1 = p[1];
        mv[0] = fmaxf(mv[0], x0.x); mv[1] = fmaxf(mv[1], x0.y);
        mv[2] = fmaxf(mv[2], x0.z); mv[3] = fmaxf(mv[3], x0.w);
        mv[4] = fmaxf(mv[4], x1.x); mv[5] = fmaxf(mv[5], x1.y);
        mv[6] = fmaxf(mv[6], x1.z); mv[7] = fmaxf(mv[7], x1.w);
    }
    #pragma unroll
    for (int m = 0; m < 8; m++) {
        #pragma unroll
        for (int o = 16; o; o >>= 1) mv[m] = fmaxf(mv[m], __shfl_xor_sync(0xffffffffu, mv[m], o));
    }
    if (lane == 0) {
        #pragma unroll
        for (int m = 0; m < 8; m++) sredm[warp][m] = mv[m];
    }
    __syncthreads();
    float mm[8];
    #pragma unroll
    for (int m = 0; m < 8; m++) {
        float v = sredm[0][m];
        #pragma unroll
        for (int w = 1; w < 8; w++) v = fmaxf(v, sredm[w][m]);
        mm[m] = v;
    }

    float sv[8] = {0,0,0,0,0,0,0,0};
    for (int b = b0 + tid; b < b1; b += 256) {
        const float4* p = (const float4*)(ak + (size_t)b * FM + f * 8);
        float4 x0 = p[0], x1 = p[1];
        sv[0] += __expf(x0.x - mm[0]); sv[1] += __expf(x0.y - mm[1]);
        sv[2] += __expf(x0.z - mm[2]); sv[3] += __expf(x0.w - mm[3]);
        sv[4] += __expf(x1.x - mm[4]); sv[5] += __expf(x1.y - mm[5]);
        sv[6] += __expf(x1.z - mm[6]); sv[7] += __expf(x1.w - mm[7]);
    }
    #pragma unroll
    for (int m = 0; m < 8; m++) {
        #pragma unroll
        for (int o = 16; o; o >>= 1) sv[m] += __shfl_xor_sync(0xffffffffu, sv[m], o);
    }
    if (lane == 0) {
        #pragma unroll
        for (int m = 0; m < 8; m++) sreds[warp][m] = sv[m];
    }
    __syncthreads();
    if (tid < 8) {
        float s = 0.f;
        #pragma unroll
        for (int w = 0; w < 8; w++) s += sreds[w][tid];
        mxq[q * FM + f * 8 + tid] = mm[tid];
        seq[q * FM + f * 8 + tid] = s;
    }
}

__global__ __launch_bounds__(512) void k_softstats_comb(
    const float* __restrict__ mxq, const float* __restrict__ seq,
    float* __restrict__ mx, float* __restrict__ se)
{
    int i = threadIdx.x;
    if (i >= FM) return;
    float m0 = mxq[i], m1 = mxq[FM + i], m2 = mxq[2 * FM + i], m3 = mxq[3 * FM + i];
    float mg = fmaxf(fmaxf(m0, m1), fmaxf(m2, m3));
    float s = seq[i] * __expf(m0 - mg) + seq[FM + i] * __expf(m1 - mg)
            + seq[2 * FM + i] * __expf(m2 - mg) + seq[3 * FM + i] * __expf(m3 - mg);
    mx[i] = mg;
    se[i] = s;
}

// ---------------------------------------------------------------------------
// Kernel 3: two batches per block; e-pair vectorized; Phase B tensor cores.
// ---------------------------------------------------------------------------
__global__ __launch_bounds__(256, 4) void k_main(
    const int* __restrict__ iu, const int* __restrict__ ii,
    const int* __restrict__ iuf, const float* __restrict__ uidW,
    const float* __restrict__ iidW, const float* __restrict__ ibias,
    const float* __restrict__ Memw, const float* __restrict__ WA,
    const float* __restrict__ BA, const float* __restrict__ Uo,
    const float* __restrict__ ak, const float* __restrict__ mx,
    const float* __restrict__ se, float* __restrict__ out,
    int user_pad, int nbTotal)
{
    int tid = threadIdx.x, lane = tid & 31, warp = tid >> 5;
    int ep = tid & 63, grp = tid >> 6;

    extern __shared__ char smraw[];
    __nv_bfloat16* sF2b = (__nv_bfloat16*)smraw;                 // 17408
    __nv_bfloat16* sWAT = (__nv_bfloat16*)(smraw + 17408);       // 17408
    __nv_bfloat16* sHPb = (__nv_bfloat16*)(smraw + 34816);       // 8704
    float* sAm  = (float*)(smraw + 43520);                       // 1600
    float* sDP  = (float*)(smraw + 45120);                       // 2048
    float* sJ   = (float*)(smraw + 47168);                       // 224
    float* sBA2 = (float*)(smraw + 47392);                       // 256
    float* sUo2 = (float*)(smraw + 47648);                       // 256
    float* sred = (float*)(smraw + 47904);                       // 32

    // --- batch-invariant staging (once per block) ---
    if (tid < A) { sBA2[tid] = BA[tid]; sUo2[tid] = Uo[tid]; }
    #pragma unroll
    for (int it = 0; it < 16; it++) {
        int idx = tid + it * 256;
        int n = idx & 63, k = (idx >> 6) * 2;
        __nv_bfloat162 w2 = __floats2bfloat162_rn(WA[k * A + n], WA[(k + 1) * A + n]);
        *(__nv_bfloat162*)&sWAT[n * KP + k] = w2;
    }
    float2 mr[8];
    #pragma unroll
    for (int m = 0; m < 8; m++) mr[m] = *(const float2*)(Memw + m * E + ep * 2);

    for (int bi = 0; bi < 2; bi++) {
        int b = blockIdx.x * 2 + bi;
        if (b >= nbTotal) break;

        const int* fids = iuf + b * NF;
        const float* akb = ak + (size_t)b * FM;
        // att_mem weights (masked, normalized); also syncs WAT on first iter
        __syncthreads();
        for (int i = tid; i < FM; i += 256) {
            int f = i >> 3;
            float fnm = (fids[f] != user_pad) ? 1.f : 0.f;
            sAm[i] = fnm * __expf(akb[i] - mx[i]) / se[i];
        }
        __syncthreads();

        // --- Phase A: f2 (vector sAm reads) ---
        for (int f = grp; f < NF; f += 4) {
            float2 fe2 = *(const float2*)(uidW + (size_t)fids[f] * E + ep * 2);
            const float4* am4 = (const float4*)(sAm + f * 8);
            float4 a0 = am4[0], a1 = am4[1];
            float f1x, f1y;
            f1x = a0.x * mr[0].x; f1y = a0.x * mr[0].y;
            f1x = fmaf(a0.y, mr[1].x, f1x); f1y = fmaf(a0.y, mr[1].y, f1y);
            f1x = fmaf(a0.z, mr[2].x, f1x); f1y = fmaf(a0.z, mr[2].y, f1y);
            f1x = fmaf(a0.w, mr[3].x, f1x); f1y = fmaf(a0.w, mr[3].y, f1y);
            f1x = fmaf(a1.x, mr[4].x, f1x); f1y = fmaf(a1.x, mr[4].y, f1y);
            f1x = fmaf(a1.y, mr[5].x, f1x); f1y = fmaf(a1.y, mr[5].y, f1y);
            f1x = fmaf(a1.z, mr[6].x, f1x); f1y = fmaf(a1.z, mr[6].y, f1y);
            f1x = fmaf(a1.w, mr[7].x, f1x); f1y = fmaf(a1.w, mr[7].y, f1y);
            *(__nv_bfloat162*)&sF2b[f * KP + ep * 2] =
                __floats2bfloat162_rn(f1x * fe2.x, f1y * fe2.y);
        }
        __syncthreads();

        // --- Phase B: tensor-core GEMM C[64f][64a] = f2 @ WA ---
        {
            int mt = warp & 3;
            int ntb = (warp >> 2) * 4;
            float c0[4], c1[4], c2[4], c3[4];
            #pragma unroll
            for (int t = 0; t < 4; t++) { c0[t] = c1[t] = c2[t] = c3[t] = 0.f; }

            unsigned int aBase = sptr(sF2b) + (mt * 16 + (lane & 15)) * (KP * 2) + ((lane >> 4) << 4);
            unsigned int bBase = sptr(sWAT) + (lane & 7) * (KP * 2) + (((lane >> 3) & 1) << 4);

            #pragma unroll
            for (int ks = 0; ks < 8; ks++) {
                unsigned int a0, a1, a2, a3;
                LDSM_X4(a0, a1, a2, a3, aBase + ks * 32);
                #pragma unroll
                for (int t = 0; t < 4; t++) {
                    unsigned int b0, b1;
                    LDSM_X2(b0, b1, bBase + (ntb + t) * 8 * (KP * 2) + ks * 32);
                    MMA16816(c0[t], c1[t], c2[t], c3[t], a0, a1, a2, a3, b0, b1);
                }
            }
            int row = mt * 16 + (lane >> 2);
            int col0 = ntb * 8 + (lane & 3) * 2;
            #pragma unroll
            for (int t = 0; t < 4; t++) {
                int col = col0 + t * 8;
                *(__nv_bfloat162*)&sHPb[row * HPW + col] = __floats2bfloat162_rn(c0[t], c1[t]);
                *(__nv_bfloat162*)&sHPb[(row + 8) * HPW + col] = __floats2bfloat162_rn(c2[t], c3[t]);
            }
        }
        __syncthreads();

        // --- Phase C: j[f] ---
        for (int f = warp; f < NF; f += 8) {
            float2 h2 = __bfloat1622float2(*(const __nv_bfloat162*)&sHPb[f * HPW + lane * 2]);
            float2 ba = *(const float2*)&sBA2[lane * 2];
            float2 uo = *(const float2*)&sUo2[lane * 2];
            float jp = fmaxf(h2.x + ba.x, 0.f) * uo.x + fmaxf(h2.y + ba.y, 0.f) * uo.y;
            #pragma unroll
            for (int o = 16; o; o >>= 1) jp += __shfl_xor_sync(0xffffffffu, jp, o);
            if (lane == 0) {
                float fnm = (fids[f] != user_pad) ? 1.f : 0.f;
                sJ[f] = fnm * __expf(jp);
            }
        }
        __syncthreads();

        // --- Phase D: weighted friend sum, then score ---
        {
            float px = 0.f, py = 0.f;
            for (int f = grp; f < NF; f += 4) {
                float jw = sJ[f];
                float2 f2v = __bfloat1622float2(*(const __nv_bfloat162*)&sF2b[f * KP + ep * 2]);
                px = fmaf(jw, f2v.x, px);
                py = fmaf(jw, f2v.y, py);
            }
            sDP[grp * 128 + ep * 2]     = px;
            sDP[grp * 128 + ep * 2 + 1] = py;
        }
        __syncthreads();

        if (tid < 128) {
            int e = tid;
            float jsum = 0.f;
            #pragma unroll 10
            for (int f = 0; f < NF; f++) jsum += sJ[f];
            float facc = sDP[e] + sDP[128 + e] + sDP[256 + e] + sDP[384 + e];
            float user = uidW[(size_t)iu[b] * E + e] + facc / (jsum + 1e-8f);
            int it = ii[b];
            float pp = user * iidW[(size_t)it * E + e];
            #pragma unroll
            for (int o = 16; o; o >>= 1) pp += __shfl_xor_sync(0xffffffffu, pp, o);
            if (lane == 0) sred[warp] = pp;
        }
        __syncthreads();
        if (tid == 0) out[b] = sred[0] + sred[1] + sred[2] + sred[3] + ibias[ii[b]];
    }
}

// ---------------------------------------------------------------------------
extern "C" void kernel_launch(void* const* d_in, const int* in_sizes, int n_in,
                              void* d_out, int out_size)
{
    const int*   input_u  = (const int*)d_in[0];
    const int*   input_i  = (const int*)d_in[1];
    const int*   input_uf = (const int*)d_in[2];
    const float* uidW     = (const float*)d_in[3];
    const float* iidW     = (const float*)d_in[4];
    const float* i_bias   = (const float*)d_in[5];
    const float* Key      = (const float*)d_in[6];
    const float* Memw     = (const float*)d_in[7];
    const float* WA       = (const float*)d_in[8];
    const float* BA       = (const float*)d_in[9];
    const float* Uo       = (const float*)d_in[10];
    float* out = (float*)d_out;

    int nb = in_sizes[0];
    int user_pad = in_sizes[3] / E - 1;

    float *g_ak_p, *g_mx_p, *g_se_p, *g_mxq_p, *g_seq_p;
    cudaGetSymbolAddress((void**)&g_ak_p, g_ak);
    cudaGetSymbolAddress((void**)&g_mx_p, g_mx);
    cudaGetSymbolAddress((void**)&g_se_p, g_se);
    cudaGetSymbolAddress((void**)&g_mxq_p, g_mxq);
    cudaGetSymbolAddress((void**)&g_seq_p, g_seq);

    const int kmain_smem = 47936;
    static int attr_set = 0;
    if (!attr_set) {
        cudaFuncSetAttribute(k_main, cudaFuncAttributeMaxDynamicSharedMemorySize, kmain_smem);
        attr_set = 1;
    }

    k_attkey<<<nb, 256>>>(input_u, input_uf, uidW, Key, g_ak_p, user_pad);
    k_softstats_part<<<dim3(NF, 4), 256>>>(g_ak_p, g_mxq_p, g_seq_p, nb);
    k_softstats_comb<<<1, 512>>>(g_mxq_p, g_seq_p, g_mx_p, g_se_p);
    k_main<<<(nb + 1) / 2, 256, kmain_smem>>>(input_u, input_i, input_uf, uidW, iidW, i_bias,
                                              Memw, WA, BA, Uo, g_ak_p, g_mx_p, g_se_p, out,
                                              user_pad, nb);
}

// round 10
// speedup vs baseline: 4.2141x; 1.1538x over previous
#include <cuda_runtime.h>
#include <cuda_bf16.h>
#include <math_constants.h>
#include <cstdint>

#define B_MAX 4096
#define NF 50
#define E 128
#define A 64
#define M 8
#define FM (NF*M)   // 400

#define FPAD 64          // padded friend rows for mma
#define KP 136           // padded k (bf16 elems) -> 272B row stride

// Scratch (no cudaMalloc allowed)
__device__ float g_ak[B_MAX * FM];
__device__ float g_mx[FM];
__device__ float g_se[FM];
__device__ float g_mxq[4 * FM];
__device__ float g_seq[4 * FM];

__device__ __forceinline__ unsigned int sptr(const void* p) {
    return (unsigned int)__cvta_generic_to_shared(p);
}

#define LDSM_X4(r0, r1, r2, r3, addr) \
    asm volatile("ldmatrix.sync.aligned.m8n8.x4.shared.b16 {%0,%1,%2,%3}, [%4];" \
                 : "=r"(r0), "=r"(r1), "=r"(r2), "=r"(r3) : "r"(addr))
#define LDSM_X2(r0, r1, addr) \
    asm volatile("ldmatrix.sync.aligned.m8n8.x2.shared.b16 {%0,%1}, [%2];" \
                 : "=r"(r0), "=r"(r1) : "r"(addr))
#define MMA16816(c0, c1, c2, c3, a0, a1, a2, a3, b0, b1) \
    asm volatile("mma.sync.aligned.m16n8k16.row.col.f32.bf16.bf16.f32 " \
                 "{%0,%1,%2,%3}, {%4,%5,%6,%7}, {%8,%9}, {%0,%1,%2,%3};" \
                 : "+f"(c0), "+f"(c1), "+f"(c2), "+f"(c3) \
                 : "r"(a0), "r"(a1), "r"(a2), "r"(a3), "r"(b0), "r"(b1))

// ---------------------------------------------------------------------------
// Kernel 1: att_key on tensor cores (unchanged, known-good).
// ---------------------------------------------------------------------------
__global__ __launch_bounds__(256, 4) void k_attkey(
    const int* __restrict__ iu, const int* __restrict__ iuf,
    const float* __restrict__ uidW, const float* __restrict__ Key,
    float* __restrict__ akout, int user_pad)
{
    int b = blockIdx.x;
    int tid = threadIdx.x, lane = tid & 31, warp = tid >> 5;

    __shared__ __nv_bfloat16 sFeb[FPAD * KP];
    __shared__ __nv_bfloat16 sKCT[M * KP];
    __shared__ float sC[2][FPAD * M];
    __shared__ float sred[8];

    float uv = 0.f;
    if (tid < E) uv = uidW[(size_t)iu[b] * E + tid];
    float p = uv * uv;
    #pragma unroll
    for (int o = 16; o; o >>= 1) p += __shfl_xor_sync(0xffffffffu, p, o);
    if (lane == 0) sred[warp] = p;
    __syncthreads();
    float n2 = 0.f;
    #pragma unroll
    for (int w = 0; w < 8; w++) n2 += sred[w];
    float inv = 1.f / fmaxf(sqrtf(n2), 1e-12f);

    if (tid < E) {
        float un = uv * inv;
        const float4* K4 = (const float4*)(Key + tid * M);
        float4 k0 = K4[0], k1 = K4[1];
        sKCT[0 * KP + tid] = __float2bfloat16(un * k0.x);
        sKCT[1 * KP + tid] = __float2bfloat16(un * k0.y);
        sKCT[2 * KP + tid] = __float2bfloat16(un * k0.z);
        sKCT[3 * KP + tid] = __float2bfloat16(un * k0.w);
        sKCT[4 * KP + tid] = __float2bfloat16(un * k1.x);
        sKCT[5 * KP + tid] = __float2bfloat16(un * k1.y);
        sKCT[6 * KP + tid] = __float2bfloat16(un * k1.z);
        sKCT[7 * KP + tid] = __float2bfloat16(un * k1.w);
    }

    const int* fids = iuf + b * NF;
    for (int f = warp; f < NF; f += 8) {
        int fid = fids[f];
        float fnm = (fid != user_pad) ? 1.f : 0.f;
        float4 v = *(const float4*)(uidW + (size_t)fid * E + lane * 4);
        v.x *= fnm; v.y *= fnm; v.z *= fnm; v.w *= fnm;
        float s = v.x * v.x + v.y * v.y + v.z * v.z + v.w * v.w;
        #pragma unroll
        for (int o = 16; o; o >>= 1) s += __shfl_xor_sync(0xffffffffu, s, o);
        float invf = 1.f / fmaxf(sqrtf(s), 1e-12f);
        __nv_bfloat162 p0 = __floats2bfloat162_rn(v.x * invf, v.y * invf);
        __nv_bfloat162 p1 = __floats2bfloat162_rn(v.z * invf, v.w * invf);
        *(__nv_bfloat162*)&sFeb[f * KP + lane * 4]     = p0;
        *(__nv_bfloat162*)&sFeb[f * KP + lane * 4 + 2] = p1;
    }
    __syncthreads();

    {
        int mt = warp & 3, kh = warp >> 2;
        float c0 = 0.f, c1 = 0.f, c2 = 0.f, c3 = 0.f;
        unsigned int aBase = sptr(sFeb) + (mt * 16 + (lane & 15)) * (KP * 2)
                           + ((lane >> 4) << 4) + kh * 128;
        unsigned int bBase = sptr(sKCT) + (lane & 7) * (KP * 2)
                           + (((lane >> 3) & 1) << 4) + kh * 128;
        #pragma unroll
        for (int ks = 0; ks < 4; ks++) {
            unsigned int a0, a1, a2, a3, b0, b1;
            LDSM_X4(a0, a1, a2, a3, aBase + ks * 32);
            LDSM_X2(b0, b1, bBase + ks * 32);
            MMA16816(c0, c1, c2, c3, a0, a1, a2, a3, b0, b1);
        }
        int row = mt * 16 + (lane >> 2);
        int col = (lane & 3) * 2;
        sC[kh][row * M + col]           = c0;
        sC[kh][row * M + col + 1]       = c1;
        sC[kh][(row + 8) * M + col]     = c2;
        sC[kh][(row + 8) * M + col + 1] = c3;
    }
    __syncthreads();

    float* akb = akout + (size_t)b * FM;
    for (int idx = tid; idx < FM; idx += 256)
        akb[idx] = sC[0][idx] + sC[1][idx];
}

// ---------------------------------------------------------------------------
// Kernel 2a/2b: split batch-axis softmax stats (unchanged).
// ---------------------------------------------------------------------------
__global__ __launch_bounds__(256) void k_softstats_part(
    const float* __restrict__ ak, float* __restrict__ mxq,
    float* __restrict__ seq, int nb)
{
    int f = blockIdx.x, q = blockIdx.y;
    int b0 = (nb * q) >> 2, b1 = (nb * (q + 1)) >> 2;
    int tid = threadIdx.x, lane = tid & 31, warp = tid >> 5;
    __shared__ float sredm[8][8];
    __shared__ float sreds[8][8];

    float mv[8];
    #pragma unroll
    for (int m = 0; m < 8; m++) mv[m] = -CUDART_INF_F;
    for (int b = b0 + tid; b < b1; b += 256) {
        const float4* p = (const float4*)(ak + (size_t)b * FM + f * 8);
        float4 x0 = p[0], x1 = p[1];
        mv[0] = fmaxf(mv[0], x0.x); mv[1] = fmaxf(mv[1], x0.y);
        mv[2] = fmaxf(mv[2], x0.z); mv[3] = fmaxf(mv[3], x0.w);
        mv[4] = fmaxf(mv[4], x1.x); mv[5] = fmaxf(mv[5], x1.y);
        mv[6] = fmaxf(mv[6], x1.z); mv[7] = fmaxf(mv[7], x1.w);
    }
    #pragma unroll
    for (int m = 0; m < 8; m++) {
        #pragma unroll
        for (int o = 16; o; o >>= 1) mv[m] = fmaxf(mv[m], __shfl_xor_sync(0xffffffffu, mv[m], o));
    }
    if (lane == 0) {
        #pragma unroll
        for (int m = 0; m < 8; m++) sredm[warp][m] = mv[m];
    }
    __syncthreads();
    float mm[8];
    #pragma unroll
    for (int m = 0; m < 8; m++) {
        float v = sredm[0][m];
        #pragma unroll
        for (int w = 1; w < 8; w++) v = fmaxf(v, sredm[w][m]);
        mm[m] = v;
    }

    float sv[8] = {0,0,0,0,0,0,0,0};
    for (int b = b0 + tid; b < b1; b += 256) {
        const float4* p = (const float4*)(ak + (size_t)b * FM + f * 8);
        float4 x0 = p[0], x1 = p[1];
        sv[0] += __expf(x0.x - mm[0]); sv[1] += __expf(x0.y - mm[1]);
        sv[2] += __expf(x0.z - mm[2]); sv[3] += __expf(x0.w - mm[3]);
        sv[4] += __expf(x1.x - mm[4]); sv[5] += __expf(x1.y - mm[5]);
        sv[6] += __expf(x1.z - mm[6]); sv[7] += __expf(x1.w - mm[7]);
    }
    #pragma unroll
    for (int m = 0; m < 8; m++) {
        #pragma unroll
        for (int o = 16; o; o >>= 1) sv[m] += __shfl_xor_sync(0xffffffffu, sv[m], o);
    }
    if (lane == 0) {
        #pragma unroll
        for (int m = 0; m < 8; m++) sreds[warp][m] = sv[m];
    }
    __syncthreads();
    if (tid < 8) {
        float s = 0.f;
        #pragma unroll
        for (int w = 0; w < 8; w++) s += sreds[w][tid];
        mxq[q * FM + f * 8 + tid] = mm[tid];
        seq[q * FM + f * 8 + tid] = s;
    }
}

__global__ __launch_bounds__(512) void k_softstats_comb(
    const float* __restrict__ mxq, const float* __restrict__ seq,
    float* __restrict__ mx, float* __restrict__ se)
{
    int i = threadIdx.x;
    if (i >= FM) return;
    float m0 = mxq[i], m1 = mxq[FM + i], m2 = mxq[2 * FM + i], m3 = mxq[3 * FM + i];
    float mg = fmaxf(fmaxf(m0, m1), fmaxf(m2, m3));
    float s = seq[i] * __expf(m0 - mg) + seq[FM + i] * __expf(m1 - mg)
            + seq[2 * FM + i] * __expf(m2 - mg) + seq[3 * FM + i] * __expf(m3 - mg);
    mx[i] = mg;
    se[i] = s;
}

// ---------------------------------------------------------------------------
// Kernel 3: two batches per block; tensor-core GEMM with in-register epilogue
// (relu/Uo dot folded into MMA fragment registers; no sHP buffer).
// ---------------------------------------------------------------------------
__global__ __launch_bounds__(256, 4) void k_main(
    const int* __restrict__ iu, const int* __restrict__ ii,
    const int* __restrict__ iuf, const float* __restrict__ uidW,
    const float* __restrict__ iidW, const float* __restrict__ ibias,
    const float* __restrict__ Memw, const float* __restrict__ WA,
    const float* __restrict__ BA, const float* __restrict__ Uo,
    const float* __restrict__ ak, const float* __restrict__ mx,
    const float* __restrict__ se, float* __restrict__ out,
    int user_pad, int nbTotal)
{
    int tid = threadIdx.x, lane = tid & 31, warp = tid >> 5;
    int ep = tid & 63, grp = tid >> 6;

    extern __shared__ char smraw[];
    __nv_bfloat16* sF2b = (__nv_bfloat16*)smraw;                 // 17408
    __nv_bfloat16* sWAT = (__nv_bfloat16*)(smraw + 17408);       // 17408
    float*  sAm   = (float*)(smraw + 34816);                     // 1600
    float*  sDP   = (float*)(smraw + 36416);                     // 2048
    float*  sJ    = (float*)(smraw + 38464);                     // 256
    float*  sJP   = (float*)(smraw + 38720);                     // 512 (2 x 64)
    float2* sBU   = (float2*)(smraw + 39232);                    // 512
    float*  sredJ = (float*)(smraw + 39744);                     // 8
    float*  sred  = (float*)(smraw + 39752);                     // 32

    // --- batch-invariant staging (once per block) ---
    if (tid < A) sBU[tid] = make_float2(BA[tid], Uo[tid]);
    #pragma unroll
    for (int it = 0; it < 16; it++) {
        int idx = tid + it * 256;
        int n = idx & 63, k = (idx >> 6) * 2;
        __nv_bfloat162 w2 = __floats2bfloat162_rn(WA[k * A + n], WA[(k + 1) * A + n]);
        *(__nv_bfloat162*)&sWAT[n * KP + k] = w2;
    }
    float2 mr[8];
    #pragma unroll
    for (int m = 0; m < 8; m++) mr[m] = *(const float2*)(Memw + m * E + ep * 2);

    for (int bi = 0; bi < 2; bi++) {
        int b = blockIdx.x * 2 + bi;
        if (b >= nbTotal) break;

        const int* fids = iuf + b * NF;
        const float* akb = ak + (size_t)b * FM;
        __syncthreads();   // protects reuse of smem from previous batch / staging
        for (int i = tid; i < FM; i += 256) {
            int f = i >> 3;
            float fnm = (fids[f] != user_pad) ? 1.f : 0.f;
            sAm[i] = fnm * __expf(akb[i] - mx[i]) / se[i];
        }
        __syncthreads();

        // --- Phase A: f2 (vector sAm reads) ---
        for (int f = grp; f < NF; f += 4) {
            float2 fe2 = *(const float2*)(uidW + (size_t)fids[f] * E + ep * 2);
            const float4* am4 = (const float4*)(sAm + f * 8);
            float4 a0 = am4[0], a1 = am4[1];
            float f1x, f1y;
            f1x = a0.x * mr[0].x; f1y = a0.x * mr[0].y;
            f1x = fmaf(a0.y, mr[1].x, f1x); f1y = fmaf(a0.y, mr[1].y, f1y);
            f1x = fmaf(a0.z, mr[2].x, f1x); f1y = fmaf(a0.z, mr[2].y, f1y);
            f1x = fmaf(a0.w, mr[3].x, f1x); f1y = fmaf(a0.w, mr[3].y, f1y);
            f1x = fmaf(a1.x, mr[4].x, f1x); f1y = fmaf(a1.x, mr[4].y, f1y);
            f1x = fmaf(a1.y, mr[5].x, f1x); f1y = fmaf(a1.y, mr[5].y, f1y);
            f1x = fmaf(a1.z, mr[6].x, f1x); f1y = fmaf(a1.z, mr[6].y, f1y);
            f1x = fmaf(a1.w, mr[7].x, f1x); f1y = fmaf(a1.w, mr[7].y, f1y);
            *(__nv_bfloat162*)&sF2b[f * KP + ep * 2] =
                __floats2bfloat162_rn(f1x * fe2.x, f1y * fe2.y);
        }
        __syncthreads();

        // --- Phase B: MMA + in-register epilogue -> sJP[kh][row] ---
        {
            int mt = warp & 3;
            int kh = warp >> 2;
            int ntb = kh * 4;
            float c0[4], c1[4], c2[4], c3[4];
            #pragma unroll
            for (int t = 0; t < 4; t++) { c0[t] = c1[t] = c2[t] = c3[t] = 0.f; }

            unsigned int aBase = sptr(sF2b) + (mt * 16 + (lane & 15)) * (KP * 2) + ((lane >> 4) << 4);
            unsigned int bBase = sptr(sWAT) + (lane & 7) * (KP * 2) + (((lane >> 3) & 1) << 4);

            #pragma unroll
            for (int ks = 0; ks < 8; ks++) {
                unsigned int a0, a1, a2, a3;
                LDSM_X4(a0, a1, a2, a3, aBase + ks * 32);
                #pragma unroll
                for (int t = 0; t < 4; t++) {
                    unsigned int b0, b1;
                    LDSM_X2(b0, b1, bBase + (ntb + t) * 8 * (KP * 2) + ks * 32);
                    MMA16816(c0[t], c1[t], c2[t], c3[t], a0, a1, a2, a3, b0, b1);
                }
            }

            // epilogue: jp(row) = sum_col relu(C+BA)*Uo over this warp's 32 cols
            float jp0 = 0.f, jp1 = 0.f;
            #pragma unroll
            for (int t = 0; t < 4; t++) {
                int col = ntb * 8 + t * 8 + (lane & 3) * 2;
                float2 bu0 = sBU[col], bu1 = sBU[col + 1];
                jp0 += fmaxf(c0[t] + bu0.x, 0.f) * bu0.y + fmaxf(c1[t] + bu1.x, 0.f) * bu1.y;
                jp1 += fmaxf(c2[t] + bu0.x, 0.f) * bu0.y + fmaxf(c3[t] + bu1.x, 0.f) * bu1.y;
            }
            jp0 += __shfl_xor_sync(0xffffffffu, jp0, 1);
            jp0 += __shfl_xor_sync(0xffffffffu, jp0, 2);
            jp1 += __shfl_xor_sync(0xffffffffu, jp1, 1);
            jp1 += __shfl_xor_sync(0xffffffffu, jp1, 2);
            if ((lane & 3) == 0) {
                int row = mt * 16 + (lane >> 2);
                sJP[kh * 64 + row]     = jp0;
                sJP[kh * 64 + row + 8] = jp1;
            }
        }
        __syncthreads();

        // --- j[f] + jsum (64 threads) ---
        if (tid < 64) {
            float j = 0.f;
            if (tid < NF) {
                float fnm = (fids[tid] != user_pad) ? 1.f : 0.f;
                j = fnm * __expf(sJP[tid] + sJP[64 + tid]);
                sJ[tid] = j;
            }
            float jj = j;
            #pragma unroll
            for (int o = 16; o; o >>= 1) jj += __shfl_xor_sync(0xffffffffu, jj, o);
            if (lane == 0) sredJ[warp] = jj;
        }
        __syncthreads();

        // --- Phase D: weighted friend sum, then score ---
        {
            float px = 0.f, py = 0.f;
            for (int f = grp; f < NF; f += 4) {
                float jw = sJ[f];
                float2 f2v = __bfloat1622float2(*(const __nv_bfloat162*)&sF2b[f * KP + ep * 2]);
                px = fmaf(jw, f2v.x, px);
                py = fmaf(jw, f2v.y, py);
            }
            sDP[grp * 128 + ep * 2]     = px;
            sDP[grp * 128 + ep * 2 + 1] = py;
        }
        __syncthreads();

        if (tid < 128) {
            int e = tid;
            float jsum = sredJ[0] + sredJ[1];
            float facc = sDP[e] + sDP[128 + e] + sDP[256 + e] + sDP[384 + e];
            float user = uidW[(size_t)iu[b] * E + e] + facc / (jsum + 1e-8f);
            int it = ii[b];
            float pp = user * iidW[(size_t)it * E + e];
            #pragma unroll
            for (int o = 16; o; o >>= 1) pp += __shfl_xor_sync(0xffffffffu, pp, o);
            if (lane == 0) sred[warp] = pp;
        }
        __syncthreads();
        if (tid == 0) out[b] = sred[0] + sred[1] + sred[2] + sred[3] + ibias[ii[b]];
    }
}

// ---------------------------------------------------------------------------
extern "C" void kernel_launch(void* const* d_in, const int* in_sizes, int n_in,
                              void* d_out, int out_size)
{
    const int*   input_u  = (const int*)d_in[0];
    const int*   input_i  = (const int*)d_in[1];
    const int*   input_uf = (const int*)d_in[2];
    const float* uidW     = (const float*)d_in[3];
    const float* iidW     = (const float*)d_in[4];
    const float* i_bias   = (const float*)d_in[5];
    const float* Key      = (const float*)d_in[6];
    const float* Memw     = (const float*)d_in[7];
    const float* WA       = (const float*)d_in[8];
    const float* BA       = (const float*)d_in[9];
    const float* Uo       = (const float*)d_in[10];
    float* out = (float*)d_out;

    int nb = in_sizes[0];
    int user_pad = in_sizes[3] / E - 1;

    float *g_ak_p, *g_mx_p, *g_se_p, *g_mxq_p, *g_seq_p;
    cudaGetSymbolAddress((void**)&g_ak_p, g_ak);
    cudaGetSymbolAddress((void**)&g_mx_p, g_mx);
    cudaGetSymbolAddress((void**)&g_se_p, g_se);
    cudaGetSymbolAddress((void**)&g_mxq_p, g_mxq);
    cudaGetSymbolAddress((void**)&g_seq_p, g_seq);

    const int kmain_smem = 39808;
    static int attr_set = 0;
    if (!attr_set) {
        cudaFuncSetAttribute(k_main, cudaFuncAttributeMaxDynamicSharedMemorySize, kmain_smem);
        attr_set = 1;
    }

    k_attkey<<<nb, 256>>>(input_u, input_uf, uidW, Key, g_ak_p, user_pad);
    k_softstats_part<<<dim3(NF, 4), 256>>>(g_ak_p, g_mxq_p, g_seq_p, nb);
    k_softstats_comb<<<1, 512>>>(g_mxq_p, g_seq_p, g_mx_p, g_se_p);
    k_main<<<(nb + 1) / 2, 256, kmain_smem>>>(input_u, input_i, input_uf, uidW, iidW, i_bias,
                                              Memw, WA, BA, Uo, g_ak_p, g_mx_p, g_se_p, out,
                                              user_pad, nb);
}